// round 9
// baseline (speedup 1.0000x reference)
#include <cuda_runtime.h>
#include <math.h>
#include <stdint.h>

#define BATCH 16
#define CHAN  256
#define HH    64
#define WW    64
#define HWSZ  4096
#define NHW   65536   // BATCH*HH*WW
#define EPSBN 1e-5f

// ---------------- scratch (device globals; no allocation allowed) ----------------
__device__ float g_t1[BATCH*CHAN*HWSZ];                   // conv1 output (fp32)
__device__ float g_u [BATCH*CHAN*HWSZ];                   // conv2 output (pre-bn2)
__device__ float g_v [BATCH*CHAN*HWSZ];                   // shortcut output (pre-bns)
__device__ __align__(16) uint32_t g_a [BATCH*CHAN*HWSZ];  // silu(bn1(t1)) tf32
__device__ __align__(16) uint32_t g_xm[BATCH*CHAN*HWSZ];  // x*mod tf32
__device__ __align__(16) uint32_t g_w2t [CHAN*CHAN];      // w_conv2^T tf32 [ci][co]
__device__ __align__(16) uint32_t g_wsct[CHAN*CHAN];      // w_sc^T   tf32 [ci][co]
__device__ __align__(16) uint32_t g_w1t[9*CHAN*CHAN];     // w_conv1 tf32 [tap][ci][co]
__device__ float g_spatial[BATCH*CHAN];
__device__ float g_mod    [BATCH*CHAN];
// [0:C) sum_t1, [C:2C) sq_t1, [2C:3C) sum_u, [3C:4C) sq_u, [4C:5C) sum_v, [5C:6C) sq_v
__device__ float g_stats[6*CHAN];

__device__ __forceinline__ float sigmoidf_(float z) { return 1.f / (1.f + expf(-z)); }
__device__ __forceinline__ float siluf_(float z)    { return z / (1.f + expf(-z)); }

__device__ __forceinline__ uint32_t f2tf32(float f) {
    uint32_t u;
    asm("cvt.rna.tf32.f32 %0, %1;" : "=r"(u) : "f"(f));
    return u;
}

__device__ __forceinline__ void mma_tf32(float* c, uint32_t a0, uint32_t a1,
                                         uint32_t a2, uint32_t a3,
                                         uint32_t b0, uint32_t b1) {
    asm volatile(
        "mma.sync.aligned.m16n8k8.row.col.f32.tf32.tf32.f32 "
        "{%0,%1,%2,%3}, {%4,%5,%6,%7}, {%8,%9}, {%0,%1,%2,%3};"
        : "+f"(c[0]), "+f"(c[1]), "+f"(c[2]), "+f"(c[3])
        : "r"(a0), "r"(a1), "r"(a2), "r"(a3), "r"(b0), "r"(b1));
}

__device__ __forceinline__ uint32_t smem_addr_u32(const void* p) {
    uint32_t a;
    asm("{ .reg .u64 t; cvta.to.shared.u64 t, %1; cvt.u32.u64 %0, t; }"
        : "=r"(a) : "l"(p));
    return a;
}
__device__ __forceinline__ void cp_async4_zfill(uint32_t dst, const void* src, int srcsz) {
    asm volatile("cp.async.ca.shared.global [%0], [%1], 4, %2;"
                 :: "r"(dst), "l"(src), "r"(srcsz));
}
__device__ __forceinline__ void cp_async16(uint32_t dst, const void* src) {
    asm volatile("cp.async.cg.shared.global [%0], [%1], 16;" :: "r"(dst), "l"(src));
}
__device__ __forceinline__ void cp_async_commit() {
    asm volatile("cp.async.commit_group;");
}
__device__ __forceinline__ void cp_async_wait0() {
    asm volatile("cp.async.wait_group 0;" ::: "memory");
}

// ---------------- zero the stats accumulators ----------------
__global__ void k_zero_stats() {
    int i = blockIdx.x * blockDim.x + threadIdx.x;
    if (i < 6*CHAN) g_stats[i] = 0.f;
}

// ---------------- spatial proj via edge-sum decomposition (one pass) ----------------
__global__ void k_spatial(const float* __restrict__ x, const float* __restrict__ w_ch) {
    int bc = blockIdx.x;
    int c  = bc & (CHAN-1);
    const float* xp = x + (size_t)bc * HWSZ;
    int tid = threadIdx.x;
    int w = tid & 63;

    float T = 0.f, R0 = 0.f, R1 = 0.f, C0 = 0.f, C1 = 0.f;
    for (int i = tid; i < HWSZ; i += 256) {
        int h = i >> 6;
        float v = xp[i];
        T += v;
        if (h == 0)  R0 += v;
        if (h == 63) R1 += v;
        if (w == 0)  C0 += v;
        if (w == 63) C1 += v;
    }
    __shared__ float red[5];
    if (tid < 5) red[tid] = 0.f;
    __syncthreads();
#pragma unroll
    for (int o = 16; o > 0; o >>= 1) {
        T  += __shfl_xor_sync(0xffffffffu, T,  o);
        R0 += __shfl_xor_sync(0xffffffffu, R0, o);
        R1 += __shfl_xor_sync(0xffffffffu, R1, o);
        C0 += __shfl_xor_sync(0xffffffffu, C0, o);
        C1 += __shfl_xor_sync(0xffffffffu, C1, o);
    }
    if ((tid & 31) == 0) {
        atomicAdd(&red[0], T);
        atomicAdd(&red[1], R0);
        atomicAdd(&red[2], R1);
        atomicAdd(&red[3], C0);
        atomicAdd(&red[4], C1);
    }
    __syncthreads();
    if (tid == 0) {
        float Tt = red[0], tR0 = red[1], tR1 = red[2], tC0 = red[3], tC1 = red[4];
        float c00 = xp[0], c0W = xp[63], cH0 = xp[63*64], cHW = xp[4095];
        float acc = 0.f;
#pragma unroll
        for (int t = 0; t < 9; t++) {
            int dy = t / 3 - 1, dx = t % 3 - 1;
            float s = Tt;
            if (dy == 1)  s -= tR0; else if (dy == -1) s -= tR1;
            if (dx == 1)  s -= tC0; else if (dx == -1) s -= tC1;
            if (dy == 1  && dx == 1)  s += c00;
            if (dy == 1  && dx == -1) s += c0W;
            if (dy == -1 && dx == 1)  s += cH0;
            if (dy == -1 && dx == -1) s += cHW;
            acc += w_ch[c*9 + t] * s;
        }
        g_spatial[bc] = acc * (1.f / (float)HWSZ);
    }
}

// ---------------- gate MLP -> g_mod ----------------
__global__ void k_mod(const float* __restrict__ dce, const float* __restrict__ w_dce,
                      const float* __restrict__ b_dce, const float* __restrict__ w_sh,
                      const float* __restrict__ b_sh, const float* __restrict__ w_ex,
                      const float* __restrict__ b_ex) {
    int b = blockIdx.x;
    int t = threadIdx.x;                 // 128 threads
    __shared__ float pooled[128];
    __shared__ float mbuf[256];
    __shared__ float hbuf[128];

    {
        float s = 0.f;
        const float* dp = dce + (size_t)b * 100 * 128 + t;
        for (int l = 0; l < 100; l++) s += dp[l * 128];
        pooled[t] = s * 0.01f;
    }
    __syncthreads();

    for (int co = t; co < 256; co += 128) {
        float a = b_dce[co];
        const float* wr = w_dce + (size_t)co * 128;
        for (int j = 0; j < 128; j++) a += pooled[j] * wr[j];
        mbuf[co] = a * g_spatial[b*CHAN + co];
    }
    __syncthreads();

    {
        float a = b_sh[t];
        const float* wr = w_sh + (size_t)t * 256;
        for (int i = 0; i < 256; i++) a += mbuf[i] * wr[i];
        hbuf[t] = fmaxf(a, 0.f);
    }
    __syncthreads();

    for (int co = t; co < 256; co += 128) {
        float a = b_ex[co];
        const float* wr = w_ex + (size_t)co * 128;
        for (int i = 0; i < 128; i++) a += hbuf[i] * wr[i];
        g_mod[b*CHAN + co] = sigmoidf_(a);
    }
}

// ---------------- transpose 1x1 weights (to tf32) ----------------
__global__ void k_transpose(const float* __restrict__ w2, const float* __restrict__ wsc) {
    int idx = blockIdx.x * blockDim.x + threadIdx.x;
    if (idx >= CHAN*CHAN) return;
    int co = idx >> 8, ci = idx & 255;
    g_w2t [ci*CHAN + co] = f2tf32(w2 [idx]);
    g_wsct[ci*CHAN + co] = f2tf32(wsc[idx]);
}

// ---------------- conv1 weights to [tap][ci][co], tf32 ----------------
__global__ void k_w1t(const float* __restrict__ w1) {
    int idx = blockIdx.x * blockDim.x + threadIdx.x;
    if (idx >= 9*CHAN*CHAN) return;
    int tap = idx >> 16;
    int rem = idx & 65535;
    int ci  = rem >> 8;
    int co  = rem & 255;
    g_w1t[idx] = f2tf32(w1[(size_t)co*2304 + ci*9 + tap]);
}

// ---------------- xm = tf32(x*mod), materialized once ----------------
__global__ void k_xm(const float* __restrict__ x) {
    int i4 = blockIdx.x * blockDim.x + threadIdx.x;
    size_t base = (size_t)i4 * 4;
    if (base >= (size_t)BATCH*CHAN*HWSZ) return;
    int c = (int)((base >> 12) & 255);
    int b = (int)(base >> 20);
    float mv = g_mod[b*CHAN + c];
    float4 xv = *(const float4*)&x[base];
    uint4 m;
    m.x = f2tf32(xv.x * mv);
    m.y = f2tf32(xv.y * mv);
    m.z = f2tf32(xv.z * mv);
    m.w = f2tf32(xv.w * mv);
    *reinterpret_cast<uint4*>(&g_xm[base]) = m;
}

// ---------------- conv1 via tf32 mma.sync: 9 shifted GEMMs, double-buffered cp.async ----------
// Block tile: M=128 pixels (16 rows x 8 cols), N=128 couts.
// Warps 4(M) x 2(N): each warp M=32 pixels (4 rows), N=64 couts.
// Two full smem stages (A patch + 9-tap B) -> fill of iter i+1 overlaps MMA of iter i.
#define PSTR 185                          // words per channel patch row (18*10 + pad)
#define BST  132                          // words per B row (128 couts + pad)
#define CONV_BUF_WORDS (16*PSTR + 144*BST)          // 21968 words = 87872 B per stage
#define CONV_SMEM_BYTES (2*CONV_BUF_WORDS*4)        // 175744 B
__global__ void __launch_bounds__(256) k_conv1_mma() {
    extern __shared__ __align__(16) uint32_t smw[];

    __shared__ float s_sum[128], s_sq[128];

    int b    = blockIdx.z;
    int co0  = blockIdx.y * 128;
    int tile = blockIdx.x;
    int th0  = (tile >> 3) * 16;
    int tw0  = (tile & 7) * 8;

    int tid  = threadIdx.x;
    int warp = tid >> 5;
    int lane = tid & 31;
    int gid  = lane >> 2;
    int tq   = lane & 3;
    int wm   = warp & 3;
    int wn   = warp >> 2;

    if (tid < 128) { s_sum[tid] = 0.f; s_sq[tid] = 0.f; }

    uint32_t smw_a = smem_addr_u32(smw);

    float acc[2][8][4];
#pragma unroll
    for (int t = 0; t < 2; t++)
#pragma unroll
        for (int j = 0; j < 8; j++)
#pragma unroll
            for (int k = 0; k < 4; k++) acc[t][j][k] = 0.f;

    // fill stage: issue all cp.asyncs for channel block c0 into buffer `buf`
    auto fill = [&](int c0, int buf) {
        uint32_t base_a = smw_a + (uint32_t)buf * (CONV_BUF_WORDS*4u);
        uint32_t base_b = base_a + (uint32_t)(16*PSTR)*4u;
        // A halo patch (zfill OOB)
        for (int idx = tid; idx < 16*180; idx += 256) {
            int ci = idx / 180, r = idx - ci*180;
            int iy = r / 10, ix = r - iy*10;
            int gh = th0 + iy - 1, gw = tw0 + ix - 1;
            bool ok = (gh >= 0) && (gh < HH) && (gw >= 0) && (gw < WW);
            const uint32_t* src = g_xm + (size_t)(b*CHAN + c0 + ci)*HWSZ
                                + (ok ? (gh*WW + gw) : 0);
            cp_async4_zfill(base_a + (uint32_t)(ci*PSTR + r)*4u, src, ok ? 4 : 0);
        }
        // all 9 taps of B: 18432 words = 4608 x 16B
        for (int idx4 = tid; idx4 < 4608; idx4 += 256) {
            int w   = idx4 * 4;
            int tap = w >> 11;            // 2048 words per tap (16ci x 128co)
            int rem = w & 2047;
            int p   = rem >> 7;           // ci 0..15
            int co4 = rem & 127;
            const uint32_t* src = g_w1t + (size_t)tap*65536 + (size_t)(c0+p)*256
                                + co0 + co4;
            cp_async16(base_b + (uint32_t)((tap*16 + p)*BST + co4)*4u, src);
        }
    };

    // prologue: stage 0
    fill(0, 0);
    cp_async_commit();

    for (int iter = 0; iter < 16; iter++) {
        cp_async_wait0();       // stage `iter` landed
        __syncthreads();        // visible to all; all warps done with the other buffer

        if (iter < 15) {        // prefetch stage iter+1 into the other buffer
            fill((iter + 1) * 16, (iter + 1) & 1);
            cp_async_commit();
        }

        const uint32_t* s_in = smw + (iter & 1) * CONV_BUF_WORDS;
        const uint32_t* s_b  = s_in + 16*PSTR;

        // ---- mainloop: 9 taps x 2 k-halves, 32 MMAs each ----
        for (int tap = 0; tap < 9; tap++) {
            int ky = tap / 3, kx = tap - ky*3;
#pragma unroll
            for (int kh = 0; kh < 2; kh++) {
                uint32_t a0[2], a1[2], a2[2], a3[2];
#pragma unroll
                for (int t = 0; t < 2; t++) {
                    int arow = (wm*4 + 2*t + ky)*10 + gid + kx;
                    const uint32_t* ap = s_in + (kh*8 + tq)*PSTR + arow;
                    a0[t] = ap[0];
                    a1[t] = ap[10];        // m+8 (next pixel row)
                    a2[t] = ap[4*PSTR];    // k+4
                    a3[t] = ap[4*PSTR + 10];
                }
                const uint32_t* bp = s_b + (tap*16 + kh*8 + tq)*BST + wn*64 + gid;
#pragma unroll
                for (int j = 0; j < 8; j++) {
                    uint32_t b0 = bp[j*8];
                    uint32_t b1 = bp[j*8 + 4*BST];   // k+4
#pragma unroll
                    for (int t = 0; t < 2; t++)
                        mma_tf32(acc[t][j], a0[t], a1[t], a2[t], a3[t], b0, b1);
                }
            }
        }
    }

    // ---- store + bn1 partial stats ----
    int px = tw0 + gid;
#pragma unroll
    for (int t = 0; t < 2; t++) {
        int gr = th0 + wm*4 + t*2;
#pragma unroll
        for (int j = 0; j < 8; j++) {
            int col = wn*64 + j*8 + tq*2;
            int co  = co0 + col;
            size_t o0 = (((size_t)b*CHAN + co)*HH + gr)*WW + px;
            float c0v = acc[t][j][0], c1v = acc[t][j][1];
            float c2v = acc[t][j][2], c3v = acc[t][j][3];
            g_t1[o0]             = c0v;
            g_t1[o0 + HWSZ]      = c1v;   // co+1
            g_t1[o0 + WW]        = c2v;   // row+1
            g_t1[o0 + HWSZ + WW] = c3v;

            float s0 = c0v + c2v;
            float s1 = c1v + c3v;
            float q0 = c0v*c0v + c2v*c2v;
            float q1 = c1v*c1v + c3v*c3v;
#pragma unroll
            for (int o = 4; o < 32; o <<= 1) {
                s0 += __shfl_xor_sync(0xffffffffu, s0, o);
                s1 += __shfl_xor_sync(0xffffffffu, s1, o);
                q0 += __shfl_xor_sync(0xffffffffu, q0, o);
                q1 += __shfl_xor_sync(0xffffffffu, q1, o);
            }
            if (gid == 0) {
                atomicAdd(&s_sum[col],     s0);
                atomicAdd(&s_sum[col + 1], s1);
                atomicAdd(&s_sq [col],     q0);
                atomicAdd(&s_sq [col + 1], q1);
            }
        }
    }
    __syncthreads();
    if (tid < 128) {
        atomicAdd(&g_stats[co0 + tid],        s_sum[tid]);
        atomicAdd(&g_stats[CHAN + co0 + tid], s_sq[tid]);
    }
}

// ---------------- prep: g_a = tf32(silu(bn1(t1))) (MUFU in a bandwidth-bound pass) ----------
__global__ void k_prep(const float* __restrict__ g1, const float* __restrict__ be1) {
    int i4 = blockIdx.x * blockDim.x + threadIdx.x;
    size_t base = (size_t)i4 * 4;
    if (base >= (size_t)BATCH*CHAN*HWSZ) return;
    int c = (int)((base >> 12) & 255);

    float mean = g_stats[c] * (1.f / (float)NHW);
    float var  = g_stats[CHAN + c] * (1.f / (float)NHW) - mean*mean;
    float sc   = g1[c] * rsqrtf(var + EPSBN);
    float sh   = be1[c] - mean * sc;

    float4 t = *(const float4*)&g_t1[base];
    uint4 a;
    a.x = f2tf32(siluf_(fmaf(t.x, sc, sh)));
    a.y = f2tf32(siluf_(fmaf(t.y, sc, sh)));
    a.z = f2tf32(siluf_(fmaf(t.z, sc, sh)));
    a.w = f2tf32(siluf_(fmaf(t.w, sc, sh)));
    *reinterpret_cast<uint4*>(&g_a[base]) = a;
}

// ---------------- fused 1x1 GEMMs, split by path:
//   path 0: u = w2  @ g_a     path 1: v = wsc @ g_xm
// grid (B*H = 1024, 2). Block: M=64 pixels (one row), N=256 couts.
#define APCH 68    // uint2 pitch for A tile (64 + pad)
#define WPCH 260   // uint2 pitch for W tile (256 couts + pad)
__global__ void __launch_bounds__(256) k_gemm_mma2() {
    __shared__ uint2 sA[16*APCH];
    __shared__ uint2 sW[16*WPCH];
    __shared__ float s_s[CHAN], s_q[CHAN];

    int bh   = blockIdx.x;
    int b    = bh >> 6;
    int h    = bh & 63;
    int path = blockIdx.y;          // 0 = u, 1 = v
    int tid  = threadIdx.x;
    int warp = tid >> 5;
    int lane = tid & 31;
    int gid  = lane >> 2;
    int tq   = lane & 3;
    int mt   = (warp & 1) * 32;
    int n0   = (warp >> 1) * 64;

    s_s[tid] = 0.f;
    s_q[tid] = 0.f;

    float acc[2][8][4];
#pragma unroll
    for (int t = 0; t < 2; t++)
#pragma unroll
        for (int j = 0; j < 8; j++)
#pragma unroll
            for (int k = 0; k < 4; k++) acc[t][j][k] = 0.f;

    const uint32_t* wsrc = path ? g_wsct : g_w2t;
    const uint32_t* asrc = path ? g_xm   : g_a;
    size_t rowb = ((size_t)b*CHAN*HH + h)*WW;

    for (int c0 = 0; c0 < CHAN; c0 += 32) {
        __syncthreads();
        // A tile: 16 pair-rows x 64 pixels (pure copy)
        for (int idx = tid; idx < 1024; idx += 256) {
            int pr = idx >> 6, p = idx & 63;
            int cin = c0 + (pr >> 2)*8 + (pr & 3);
            size_t gi = rowb + (size_t)cin*HWSZ + p;
            uint2 val;
            val.x = asrc[gi];
            val.y = asrc[gi + 4*HWSZ];
            sA[pr*APCH + p] = val;
        }
        // W tile: 16 pair-rows x 256 couts (pair-packed)
        for (int idx = tid; idx < 1024; idx += 256) {
            int pr = idx >> 6, c4 = idx & 63;
            int cin = c0 + (pr >> 2)*8 + (pr & 3);
            const uint32_t* src = wsrc + (size_t)cin*CHAN + c4*4;
            uint4 wa = *reinterpret_cast<const uint4*>(src);
            uint4 wb = *reinterpret_cast<const uint4*>(src + 4*CHAN);
            uint2* dst = sW + pr*WPCH + c4*4;
            *reinterpret_cast<uint4*>(dst)     = make_uint4(wa.x, wb.x, wa.y, wb.y);
            *reinterpret_cast<uint4*>(dst + 2) = make_uint4(wa.z, wb.z, wa.w, wb.w);
        }
        __syncthreads();

#pragma unroll
        for (int kh = 0; kh < 4; kh++) {
            uint2 aL[2], aH[2];
#pragma unroll
            for (int t = 0; t < 2; t++) {
                const uint2* ap = sA + (kh*4 + tq)*APCH + mt + t*16 + gid;
                aL[t] = ap[0];
                aH[t] = ap[8];
            }
            const uint2* bp = sW + (kh*4 + tq)*WPCH + n0 + gid;
#pragma unroll
            for (int j = 0; j < 8; j++) {
                uint2 bb = bp[j*8];
#pragma unroll
                for (int t = 0; t < 2; t++)
                    mma_tf32(acc[t][j], aL[t].x, aH[t].x, aL[t].y, aH[t].y, bb.x, bb.y);
            }
        }
    }

    float* gout = path ? g_v : g_u;
#pragma unroll
    for (int t = 0; t < 2; t++) {
        int p = mt + t*16 + gid;
#pragma unroll
        for (int j = 0; j < 8; j++) {
            int co = n0 + j*8 + tq*2;
            size_t o0 = (((size_t)b*CHAN + co)*HH + h)*WW + p;
            float c0v = acc[t][j][0], c1v = acc[t][j][1];
            float c2v = acc[t][j][2], c3v = acc[t][j][3];
            gout[o0]            = c0v;
            gout[o0 + HWSZ]     = c1v;   // co+1
            gout[o0 + 8]        = c2v;   // p+8
            gout[o0 + HWSZ + 8] = c3v;

            float s0 = c0v + c2v;
            float s1 = c1v + c3v;
            float q0 = c0v*c0v + c2v*c2v;
            float q1 = c1v*c1v + c3v*c3v;
#pragma unroll
            for (int o = 4; o < 32; o <<= 1) {
                s0 += __shfl_xor_sync(0xffffffffu, s0, o);
                s1 += __shfl_xor_sync(0xffffffffu, s1, o);
                q0 += __shfl_xor_sync(0xffffffffu, q0, o);
                q1 += __shfl_xor_sync(0xffffffffu, q1, o);
            }
            if (gid == 0) {
                atomicAdd(&s_s[co],     s0);
                atomicAdd(&s_s[co + 1], s1);
                atomicAdd(&s_q[co],     q0);
                atomicAdd(&s_q[co + 1], q1);
            }
        }
    }
    __syncthreads();
    {
        int soff = 2*CHAN + 2*CHAN*path;
        atomicAdd(&g_stats[soff + tid],        s_s[tid]);
        atomicAdd(&g_stats[soff + CHAN + tid], s_q[tid]);
    }
}

// ---------------- final: out = silu(bn2(u) + bns(v)) ----------------
__global__ void k_final(float* __restrict__ out,
                        const float* __restrict__ g2, const float* __restrict__ be2,
                        const float* __restrict__ gs, const float* __restrict__ bes) {
    int i4 = blockIdx.x * blockDim.x + threadIdx.x;
    size_t base = (size_t)i4 * 4;
    if (base >= (size_t)BATCH*CHAN*HWSZ) return;
    int c = (int)((base >> 12) & 255);

    float mu = g_stats[2*CHAN + c] * (1.f / (float)NHW);
    float vu = g_stats[3*CHAN + c] * (1.f / (float)NHW) - mu*mu;
    float su = g2[c] * rsqrtf(vu + EPSBN);
    float bu = be2[c] - mu * su;

    float mv = g_stats[4*CHAN + c] * (1.f / (float)NHW);
    float vv = g_stats[5*CHAN + c] * (1.f / (float)NHW) - mv*mv;
    float sv = gs[c] * rsqrtf(vv + EPSBN);
    float bv = bes[c] - mv * sv;

    float4 u = *(const float4*)&g_u[base];
    float4 v = *(const float4*)&g_v[base];
    float4 o;
    {
        float z;
        z = fmaf(u.x, su, bu) + fmaf(v.x, sv, bv); o.x = siluf_(z);
        z = fmaf(u.y, su, bu) + fmaf(v.y, sv, bv); o.y = siluf_(z);
        z = fmaf(u.z, su, bu) + fmaf(v.z, sv, bv); o.z = siluf_(z);
        z = fmaf(u.w, su, bu) + fmaf(v.w, sv, bv); o.w = siluf_(z);
    }
    *(float4*)&out[base] = o;
}

// ---------------- launch ----------------
extern "C" void kernel_launch(void* const* d_in, const int* in_sizes, int n_in,
                              void* d_out, int out_size) {
    const float* x        = (const float*)d_in[0];
    const float* dce      = (const float*)d_in[1];
    const float* w_dce    = (const float*)d_in[2];
    const float* b_dce    = (const float*)d_in[3];
    const float* w_ch     = (const float*)d_in[4];
    const float* w_shrink = (const float*)d_in[5];
    const float* b_shrink = (const float*)d_in[6];
    const float* w_expand = (const float*)d_in[7];
    const float* b_expand = (const float*)d_in[8];
    const float* w_conv1  = (const float*)d_in[9];
    const float* g_bn1    = (const float*)d_in[10];
    const float* be_bn1   = (const float*)d_in[11];
    const float* w_conv2  = (const float*)d_in[12];
    const float* g_bn2    = (const float*)d_in[13];
    const float* be_bn2   = (const float*)d_in[14];
    const float* w_sc     = (const float*)d_in[15];
    const float* g_bns    = (const float*)d_in[16];
    const float* be_bns   = (const float*)d_in[17];
    float* out = (float*)d_out;

    cudaFuncSetAttribute(k_conv1_mma, cudaFuncAttributeMaxDynamicSharedMemorySize,
                         CONV_SMEM_BYTES);

    k_zero_stats<<<6, 256>>>();
    k_spatial<<<BATCH*CHAN, 256>>>(x, w_ch);
    k_mod<<<BATCH, 128>>>(dce, w_dce, b_dce, w_shrink, b_shrink, w_expand, b_expand);
    k_transpose<<<256, 256>>>(w_conv2, w_sc);
    k_w1t<<<(9*CHAN*CHAN + 255)/256, 256>>>(w_conv1);
    k_xm<<<(BATCH*CHAN*HWSZ/4 + 255)/256, 256>>>(x);
    k_conv1_mma<<<dim3(32, 2, BATCH), 256, CONV_SMEM_BYTES>>>();
    k_prep<<<(BATCH*CHAN*HWSZ/4 + 255)/256, 256>>>(g_bn1, be_bn1);
    k_gemm_mma2<<<dim3(BATCH*HH, 2), 256>>>();
    k_final<<<(BATCH*CHAN*HWSZ/4 + 255)/256, 256>>>(out, g_bn2, be_bn2, g_bns, be_bns);
}

// round 10
// speedup vs baseline: 1.0288x; 1.0288x over previous
#include <cuda_runtime.h>
#include <math.h>
#include <stdint.h>

#define BATCH 16
#define CHAN  256
#define HH    64
#define WW    64
#define HWSZ  4096
#define NHW   65536   // BATCH*HH*WW
#define EPSBN 1e-5f

// ---------------- scratch (device globals; no allocation allowed) ----------------
__device__ float g_t1[BATCH*CHAN*HWSZ];                   // conv1 output (fp32)
__device__ float g_u [BATCH*CHAN*HWSZ];                   // conv2 output (pre-bn2)
__device__ float g_v [BATCH*CHAN*HWSZ];                   // shortcut output (pre-bns)
__device__ __align__(16) uint32_t g_a [BATCH*CHAN*HWSZ];  // silu(bn1(t1)) tf32
__device__ __align__(16) uint32_t g_xm[BATCH*CHAN*HWSZ];  // x*mod tf32
__device__ __align__(16) uint32_t g_w2t [CHAN*CHAN];      // w_conv2^T tf32 [ci][co]
__device__ __align__(16) uint32_t g_wsct[CHAN*CHAN];      // w_sc^T   tf32 [ci][co]
__device__ __align__(16) uint32_t g_w1t[9*CHAN*CHAN];     // w_conv1 tf32 [tap][ci][co]
__device__ float g_spatial[BATCH*CHAN];
__device__ float g_mod    [BATCH*CHAN];
// [0:C) sum_t1, [C:2C) sq_t1, [2C:3C) sum_u, [3C:4C) sq_u, [4C:5C) sum_v, [5C:6C) sq_v
__device__ float g_stats[6*CHAN];

__device__ __forceinline__ float sigmoidf_(float z) { return 1.f / (1.f + expf(-z)); }
__device__ __forceinline__ float siluf_(float z)    { return z / (1.f + expf(-z)); }

__device__ __forceinline__ uint32_t f2tf32(float f) {
    uint32_t u;
    asm("cvt.rna.tf32.f32 %0, %1;" : "=r"(u) : "f"(f));
    return u;
}

__device__ __forceinline__ void mma_tf32(float* c, uint32_t a0, uint32_t a1,
                                         uint32_t a2, uint32_t a3,
                                         uint32_t b0, uint32_t b1) {
    asm volatile(
        "mma.sync.aligned.m16n8k8.row.col.f32.tf32.tf32.f32 "
        "{%0,%1,%2,%3}, {%4,%5,%6,%7}, {%8,%9}, {%0,%1,%2,%3};"
        : "+f"(c[0]), "+f"(c[1]), "+f"(c[2]), "+f"(c[3])
        : "r"(a0), "r"(a1), "r"(a2), "r"(a3), "r"(b0), "r"(b1));
}

__device__ __forceinline__ uint32_t smem_addr_u32(const void* p) {
    uint32_t a;
    asm("{ .reg .u64 t; cvta.to.shared.u64 t, %1; cvt.u32.u64 %0, t; }"
        : "=r"(a) : "l"(p));
    return a;
}
__device__ __forceinline__ void cp_async4_zfill(uint32_t dst, const void* src, int srcsz) {
    asm volatile("cp.async.ca.shared.global [%0], [%1], 4, %2;"
                 :: "r"(dst), "l"(src), "r"(srcsz));
}
__device__ __forceinline__ void cp_async16(uint32_t dst, const void* src) {
    asm volatile("cp.async.cg.shared.global [%0], [%1], 16;" :: "r"(dst), "l"(src));
}
__device__ __forceinline__ void cp_async_commit() {
    asm volatile("cp.async.commit_group;");
}
__device__ __forceinline__ void cp_async_wait0() {
    asm volatile("cp.async.wait_group 0;" ::: "memory");
}

// ---------------- spatial proj via edge-sum decomposition (one pass) ----------------
__global__ void k_spatial(const float* __restrict__ x, const float* __restrict__ w_ch) {
    int bc = blockIdx.x;
    int c  = bc & (CHAN-1);
    const float* xp = x + (size_t)bc * HWSZ;
    int tid = threadIdx.x;
    int w = tid & 63;

    float T = 0.f, R0 = 0.f, R1 = 0.f, C0 = 0.f, C1 = 0.f;
    for (int i = tid; i < HWSZ; i += 256) {
        int h = i >> 6;
        float v = xp[i];
        T += v;
        if (h == 0)  R0 += v;
        if (h == 63) R1 += v;
        if (w == 0)  C0 += v;
        if (w == 63) C1 += v;
    }
    __shared__ float red[5];
    if (tid < 5) red[tid] = 0.f;
    __syncthreads();
#pragma unroll
    for (int o = 16; o > 0; o >>= 1) {
        T  += __shfl_xor_sync(0xffffffffu, T,  o);
        R0 += __shfl_xor_sync(0xffffffffu, R0, o);
        R1 += __shfl_xor_sync(0xffffffffu, R1, o);
        C0 += __shfl_xor_sync(0xffffffffu, C0, o);
        C1 += __shfl_xor_sync(0xffffffffu, C1, o);
    }
    if ((tid & 31) == 0) {
        atomicAdd(&red[0], T);
        atomicAdd(&red[1], R0);
        atomicAdd(&red[2], R1);
        atomicAdd(&red[3], C0);
        atomicAdd(&red[4], C1);
    }
    __syncthreads();
    if (tid == 0) {
        float Tt = red[0], tR0 = red[1], tR1 = red[2], tC0 = red[3], tC1 = red[4];
        float c00 = xp[0], c0W = xp[63], cH0 = xp[63*64], cHW = xp[4095];
        float acc = 0.f;
#pragma unroll
        for (int t = 0; t < 9; t++) {
            int dy = t / 3 - 1, dx = t % 3 - 1;
            float s = Tt;
            if (dy == 1)  s -= tR0; else if (dy == -1) s -= tR1;
            if (dx == 1)  s -= tC0; else if (dx == -1) s -= tC1;
            if (dy == 1  && dx == 1)  s += c00;
            if (dy == 1  && dx == -1) s += c0W;
            if (dy == -1 && dx == 1)  s += cH0;
            if (dy == -1 && dx == -1) s += cHW;
            acc += w_ch[c*9 + t] * s;
        }
        g_spatial[bc] = acc * (1.f / (float)HWSZ);
    }
}

// ---------------- gate MLP -> g_mod ----------------
__global__ void k_mod(const float* __restrict__ dce, const float* __restrict__ w_dce,
                      const float* __restrict__ b_dce, const float* __restrict__ w_sh,
                      const float* __restrict__ b_sh, const float* __restrict__ w_ex,
                      const float* __restrict__ b_ex) {
    int b = blockIdx.x;
    int t = threadIdx.x;                 // 128 threads
    __shared__ float pooled[128];
    __shared__ float mbuf[256];
    __shared__ float hbuf[128];

    {
        float s = 0.f;
        const float* dp = dce + (size_t)b * 100 * 128 + t;
        for (int l = 0; l < 100; l++) s += dp[l * 128];
        pooled[t] = s * 0.01f;
    }
    __syncthreads();

    for (int co = t; co < 256; co += 128) {
        float a = b_dce[co];
        const float* wr = w_dce + (size_t)co * 128;
        for (int j = 0; j < 128; j++) a += pooled[j] * wr[j];
        mbuf[co] = a * g_spatial[b*CHAN + co];
    }
    __syncthreads();

    {
        float a = b_sh[t];
        const float* wr = w_sh + (size_t)t * 256;
        for (int i = 0; i < 256; i++) a += mbuf[i] * wr[i];
        hbuf[t] = fmaxf(a, 0.f);
    }
    __syncthreads();

    for (int co = t; co < 256; co += 128) {
        float a = b_ex[co];
        const float* wr = w_ex + (size_t)co * 128;
        for (int i = 0; i < 128; i++) a += hbuf[i] * wr[i];
        g_mod[b*CHAN + co] = sigmoidf_(a);
    }
}

// ---------------- transpose 1x1 weights (to tf32) ----------------
__global__ void k_transpose(const float* __restrict__ w2, const float* __restrict__ wsc) {
    int idx = blockIdx.x * blockDim.x + threadIdx.x;
    if (idx >= CHAN*CHAN) return;
    int co = idx >> 8, ci = idx & 255;
    g_w2t [ci*CHAN + co] = f2tf32(w2 [idx]);
    g_wsct[ci*CHAN + co] = f2tf32(wsc[idx]);
}

// ---------------- conv1 weights to [tap][ci][co], tf32; also zero stats ----------------
__global__ void k_w1t(const float* __restrict__ w1) {
    int idx = blockIdx.x * blockDim.x + threadIdx.x;
    if (idx < 6*CHAN) g_stats[idx] = 0.f;
    if (idx >= 9*CHAN*CHAN) return;
    int tap = idx >> 16;
    int rem = idx & 65535;
    int ci  = rem >> 8;
    int co  = rem & 255;
    g_w1t[idx] = f2tf32(w1[(size_t)co*2304 + ci*9 + tap]);
}

// ---------------- xm = tf32(x*mod), materialized once ----------------
__global__ void k_xm(const float* __restrict__ x) {
    int i4 = blockIdx.x * blockDim.x + threadIdx.x;
    size_t base = (size_t)i4 * 4;
    if (base >= (size_t)BATCH*CHAN*HWSZ) return;
    int c = (int)((base >> 12) & 255);
    int b = (int)(base >> 20);
    float mv = g_mod[b*CHAN + c];
    float4 xv = *(const float4*)&x[base];
    uint4 m;
    m.x = f2tf32(xv.x * mv);
    m.y = f2tf32(xv.y * mv);
    m.z = f2tf32(xv.z * mv);
    m.w = f2tf32(xv.w * mv);
    *reinterpret_cast<uint4*>(&g_xm[base]) = m;
}

// ---------------- conv1 via tf32 mma.sync: 9 shifted GEMMs -------------------------------
// Block tile: M=128 pixels (16 rows x 8 cols), N=128 couts.
// Warps 4(M) x 2(N): each warp M=32 pixels (4 rows), N=64 couts.
// Pipeline: 32 stages of K=8 channels, double-buffered (43.9 KB/stage, 87.9 KB total)
// -> 2 CTAs/SM occupancy preserved AND fill of stage i+1 overlaps MMA of stage i.
#define PSTR 185                          // words per channel patch row (18*10 + pad)
#define BST  132                          // words per B row (128 couts + pad)
#define CONV_BUF_WORDS (8*PSTR + 72*BST)            // 10984 words = 43936 B per stage
#define CONV_SMEM_BYTES (2*CONV_BUF_WORDS*4)        // 87872 B
__global__ void __launch_bounds__(256) k_conv1_mma() {
    extern __shared__ __align__(16) uint32_t smw[];

    __shared__ float s_sum[128], s_sq[128];

    int b    = blockIdx.z;
    int co0  = blockIdx.y * 128;
    int tile = blockIdx.x;
    int th0  = (tile >> 3) * 16;
    int tw0  = (tile & 7) * 8;

    int tid  = threadIdx.x;
    int warp = tid >> 5;
    int lane = tid & 31;
    int gid  = lane >> 2;
    int tq   = lane & 3;
    int wm   = warp & 3;
    int wn   = warp >> 2;

    if (tid < 128) { s_sum[tid] = 0.f; s_sq[tid] = 0.f; }

    uint32_t smw_a = smem_addr_u32(smw);

    float acc[2][8][4];
#pragma unroll
    for (int t = 0; t < 2; t++)
#pragma unroll
        for (int j = 0; j < 8; j++)
#pragma unroll
            for (int k = 0; k < 4; k++) acc[t][j][k] = 0.f;

    // fill stage: issue all cp.asyncs for 8-channel block c0 into buffer `buf`
    auto fill = [&](int c0, int buf) {
        uint32_t base_a = smw_a + (uint32_t)buf * (CONV_BUF_WORDS*4u);
        uint32_t base_b = base_a + (uint32_t)(8*PSTR)*4u;
        // A halo patch: 8 ch x 180 words (zfill OOB)
        for (int idx = tid; idx < 8*180; idx += 256) {
            int ci = idx / 180, r = idx - ci*180;
            int iy = r / 10, ix = r - iy*10;
            int gh = th0 + iy - 1, gw = tw0 + ix - 1;
            bool ok = (gh >= 0) && (gh < HH) && (gw >= 0) && (gw < WW);
            const uint32_t* src = g_xm + (size_t)(b*CHAN + c0 + ci)*HWSZ
                                + (ok ? (gh*WW + gw) : 0);
            cp_async4_zfill(base_a + (uint32_t)(ci*PSTR + r)*4u, src, ok ? 4 : 0);
        }
        // B: 9 taps x 8 ci x 128 co = 9216 words = 2304 x 16B
        for (int idx4 = tid; idx4 < 2304; idx4 += 256) {
            int w   = idx4 * 4;
            int tap = w >> 10;            // 1024 words per tap (8ci x 128co)
            int rem = w & 1023;
            int p   = rem >> 7;           // ci 0..7
            int co4 = rem & 127;
            const uint32_t* src = g_w1t + (size_t)tap*65536 + (size_t)(c0+p)*256
                                + co0 + co4;
            cp_async16(base_b + (uint32_t)((tap*8 + p)*BST + co4)*4u, src);
        }
    };

    // prologue: stage 0
    fill(0, 0);
    cp_async_commit();

    for (int iter = 0; iter < 32; iter++) {
        cp_async_wait0();       // stage `iter` landed
        __syncthreads();        // visible to all; all warps done with the other buffer

        if (iter < 31) {        // prefetch stage iter+1 into the other buffer
            fill((iter + 1) * 8, (iter + 1) & 1);
            cp_async_commit();
        }

        const uint32_t* s_in = smw + (iter & 1) * CONV_BUF_WORDS;
        const uint32_t* s_b  = s_in + 8*PSTR;

        // ---- mainloop: 9 taps x 16 MMAs (K=8: rows tq and tq+4) ----
        for (int tap = 0; tap < 9; tap++) {
            int ky = tap / 3, kx = tap - ky*3;
            uint32_t a0[2], a1[2], a2[2], a3[2];
#pragma unroll
            for (int t = 0; t < 2; t++) {
                int arow = (wm*4 + 2*t + ky)*10 + gid + kx;
                const uint32_t* ap = s_in + tq*PSTR + arow;
                a0[t] = ap[0];
                a1[t] = ap[10];        // m+8 (next pixel row)
                a2[t] = ap[4*PSTR];    // k+4
                a3[t] = ap[4*PSTR + 10];
            }
            const uint32_t* bp = s_b + (tap*8 + tq)*BST + wn*64 + gid;
#pragma unroll
            for (int j = 0; j < 8; j++) {
                uint32_t b0 = bp[j*8];
                uint32_t b1 = bp[j*8 + 4*BST];   // k+4
#pragma unroll
                for (int t = 0; t < 2; t++)
                    mma_tf32(acc[t][j], a0[t], a1[t], a2[t], a3[t], b0, b1);
            }
        }
    }

    // ---- store + bn1 partial stats ----
    int px = tw0 + gid;
#pragma unroll
    for (int t = 0; t < 2; t++) {
        int gr = th0 + wm*4 + t*2;
#pragma unroll
        for (int j = 0; j < 8; j++) {
            int col = wn*64 + j*8 + tq*2;
            int co  = co0 + col;
            size_t o0 = (((size_t)b*CHAN + co)*HH + gr)*WW + px;
            float c0v = acc[t][j][0], c1v = acc[t][j][1];
            float c2v = acc[t][j][2], c3v = acc[t][j][3];
            g_t1[o0]             = c0v;
            g_t1[o0 + HWSZ]      = c1v;   // co+1
            g_t1[o0 + WW]        = c2v;   // row+1
            g_t1[o0 + HWSZ + WW] = c3v;

            float s0 = c0v + c2v;
            float s1 = c1v + c3v;
            float q0 = c0v*c0v + c2v*c2v;
            float q1 = c1v*c1v + c3v*c3v;
#pragma unroll
            for (int o = 4; o < 32; o <<= 1) {
                s0 += __shfl_xor_sync(0xffffffffu, s0, o);
                s1 += __shfl_xor_sync(0xffffffffu, s1, o);
                q0 += __shfl_xor_sync(0xffffffffu, q0, o);
                q1 += __shfl_xor_sync(0xffffffffu, q1, o);
            }
            if (gid == 0) {
                atomicAdd(&s_sum[col],     s0);
                atomicAdd(&s_sum[col + 1], s1);
                atomicAdd(&s_sq [col],     q0);
                atomicAdd(&s_sq [col + 1], q1);
            }
        }
    }
    __syncthreads();
    if (tid < 128) {
        atomicAdd(&g_stats[co0 + tid],        s_sum[tid]);
        atomicAdd(&g_stats[CHAN + co0 + tid], s_sq[tid]);
    }
}

// ---------------- prep: g_a = tf32(silu(bn1(t1))) (MUFU in a bandwidth-bound pass) ----------
__global__ void k_prep(const float* __restrict__ g1, const float* __restrict__ be1) {
    int i4 = blockIdx.x * blockDim.x + threadIdx.x;
    size_t base = (size_t)i4 * 4;
    if (base >= (size_t)BATCH*CHAN*HWSZ) return;
    int c = (int)((base >> 12) & 255);

    float mean = g_stats[c] * (1.f / (float)NHW);
    float var  = g_stats[CHAN + c] * (1.f / (float)NHW) - mean*mean;
    float sc   = g1[c] * rsqrtf(var + EPSBN);
    float sh   = be1[c] - mean * sc;

    float4 t = *(const float4*)&g_t1[base];
    uint4 a;
    a.x = f2tf32(siluf_(fmaf(t.x, sc, sh)));
    a.y = f2tf32(siluf_(fmaf(t.y, sc, sh)));
    a.z = f2tf32(siluf_(fmaf(t.z, sc, sh)));
    a.w = f2tf32(siluf_(fmaf(t.w, sc, sh)));
    *reinterpret_cast<uint4*>(&g_a[base]) = a;
}

// ---------------- fused 1x1 GEMMs, split by path:
//   path 0: u = w2  @ g_a     path 1: v = wsc @ g_xm
// grid (B*H = 1024, 2). Block: M=64 pixels (one row), N=256 couts.
#define APCH 68    // uint2 pitch for A tile (64 + pad)
#define WPCH 260   // uint2 pitch for W tile (256 couts + pad)
__global__ void __launch_bounds__(256) k_gemm_mma2() {
    __shared__ uint2 sA[16*APCH];
    __shared__ uint2 sW[16*WPCH];
    __shared__ float s_s[CHAN], s_q[CHAN];

    int bh   = blockIdx.x;
    int b    = bh >> 6;
    int h    = bh & 63;
    int path = blockIdx.y;          // 0 = u, 1 = v
    int tid  = threadIdx.x;
    int warp = tid >> 5;
    int lane = tid & 31;
    int gid  = lane >> 2;
    int tq   = lane & 3;
    int mt   = (warp & 1) * 32;
    int n0   = (warp >> 1) * 64;

    s_s[tid] = 0.f;
    s_q[tid] = 0.f;

    float acc[2][8][4];
#pragma unroll
    for (int t = 0; t < 2; t++)
#pragma unroll
        for (int j = 0; j < 8; j++)
#pragma unroll
            for (int k = 0; k < 4; k++) acc[t][j][k] = 0.f;

    const uint32_t* wsrc = path ? g_wsct : g_w2t;
    const uint32_t* asrc = path ? g_xm   : g_a;
    size_t rowb = ((size_t)b*CHAN*HH + h)*WW;

    for (int c0 = 0; c0 < CHAN; c0 += 32) {
        __syncthreads();
        // A tile: 16 pair-rows x 64 pixels (pure copy)
        for (int idx = tid; idx < 1024; idx += 256) {
            int pr = idx >> 6, p = idx & 63;
            int cin = c0 + (pr >> 2)*8 + (pr & 3);
            size_t gi = rowb + (size_t)cin*HWSZ + p;
            uint2 val;
            val.x = asrc[gi];
            val.y = asrc[gi + 4*HWSZ];
            sA[pr*APCH + p] = val;
        }
        // W tile: 16 pair-rows x 256 couts (pair-packed)
        for (int idx = tid; idx < 1024; idx += 256) {
            int pr = idx >> 6, c4 = idx & 63;
            int cin = c0 + (pr >> 2)*8 + (pr & 3);
            const uint32_t* src = wsrc + (size_t)cin*CHAN + c4*4;
            uint4 wa = *reinterpret_cast<const uint4*>(src);
            uint4 wb = *reinterpret_cast<const uint4*>(src + 4*CHAN);
            uint2* dst = sW + pr*WPCH + c4*4;
            *reinterpret_cast<uint4*>(dst)     = make_uint4(wa.x, wb.x, wa.y, wb.y);
            *reinterpret_cast<uint4*>(dst + 2) = make_uint4(wa.z, wb.z, wa.w, wb.w);
        }
        __syncthreads();

#pragma unroll
        for (int kh = 0; kh < 4; kh++) {
            uint2 aL[2], aH[2];
#pragma unroll
            for (int t = 0; t < 2; t++) {
                const uint2* ap = sA + (kh*4 + tq)*APCH + mt + t*16 + gid;
                aL[t] = ap[0];
                aH[t] = ap[8];
            }
            const uint2* bp = sW + (kh*4 + tq)*WPCH + n0 + gid;
#pragma unroll
            for (int j = 0; j < 8; j++) {
                uint2 bb = bp[j*8];
#pragma unroll
                for (int t = 0; t < 2; t++)
                    mma_tf32(acc[t][j], aL[t].x, aH[t].x, aL[t].y, aH[t].y, bb.x, bb.y);
            }
        }
    }

    float* gout = path ? g_v : g_u;
#pragma unroll
    for (int t = 0; t < 2; t++) {
        int p = mt + t*16 + gid;
#pragma unroll
        for (int j = 0; j < 8; j++) {
            int co = n0 + j*8 + tq*2;
            size_t o0 = (((size_t)b*CHAN + co)*HH + h)*WW + p;
            float c0v = acc[t][j][0], c1v = acc[t][j][1];
            float c2v = acc[t][j][2], c3v = acc[t][j][3];
            gout[o0]            = c0v;
            gout[o0 + HWSZ]     = c1v;   // co+1
            gout[o0 + 8]        = c2v;   // p+8
            gout[o0 + HWSZ + 8] = c3v;

            float s0 = c0v + c2v;
            float s1 = c1v + c3v;
            float q0 = c0v*c0v + c2v*c2v;
            float q1 = c1v*c1v + c3v*c3v;
#pragma unroll
            for (int o = 4; o < 32; o <<= 1) {
                s0 += __shfl_xor_sync(0xffffffffu, s0, o);
                s1 += __shfl_xor_sync(0xffffffffu, s1, o);
                q0 += __shfl_xor_sync(0xffffffffu, q0, o);
                q1 += __shfl_xor_sync(0xffffffffu, q1, o);
            }
            if (gid == 0) {
                atomicAdd(&s_s[co],     s0);
                atomicAdd(&s_s[co + 1], s1);
                atomicAdd(&s_q[co],     q0);
                atomicAdd(&s_q[co + 1], q1);
            }
        }
    }
    __syncthreads();
    {
        int soff = 2*CHAN + 2*CHAN*path;
        atomicAdd(&g_stats[soff + tid],        s_s[tid]);
        atomicAdd(&g_stats[soff + CHAN + tid], s_q[tid]);
    }
}

// ---------------- final: out = silu(bn2(u) + bns(v)) ----------------
__global__ void k_final(float* __restrict__ out,
                        const float* __restrict__ g2, const float* __restrict__ be2,
                        const float* __restrict__ gs, const float* __restrict__ bes) {
    int i4 = blockIdx.x * blockDim.x + threadIdx.x;
    size_t base = (size_t)i4 * 4;
    if (base >= (size_t)BATCH*CHAN*HWSZ) return;
    int c = (int)((base >> 12) & 255);

    float mu = g_stats[2*CHAN + c] * (1.f / (float)NHW);
    float vu = g_stats[3*CHAN + c] * (1.f / (float)NHW) - mu*mu;
    float su = g2[c] * rsqrtf(vu + EPSBN);
    float bu = be2[c] - mu * su;

    float mv = g_stats[4*CHAN + c] * (1.f / (float)NHW);
    float vv = g_stats[5*CHAN + c] * (1.f / (float)NHW) - mv*mv;
    float sv = gs[c] * rsqrtf(vv + EPSBN);
    float bv = bes[c] - mv * sv;

    float4 u = *(const float4*)&g_u[base];
    float4 v = *(const float4*)&g_v[base];
    float4 o;
    {
        float z;
        z = fmaf(u.x, su, bu) + fmaf(v.x, sv, bv); o.x = siluf_(z);
        z = fmaf(u.y, su, bu) + fmaf(v.y, sv, bv); o.y = siluf_(z);
        z = fmaf(u.z, su, bu) + fmaf(v.z, sv, bv); o.z = siluf_(z);
        z = fmaf(u.w, su, bu) + fmaf(v.w, sv, bv); o.w = siluf_(z);
    }
    *(float4*)&out[base] = o;
}

// ---------------- launch ----------------
extern "C" void kernel_launch(void* const* d_in, const int* in_sizes, int n_in,
                              void* d_out, int out_size) {
    const float* x        = (const float*)d_in[0];
    const float* dce      = (const float*)d_in[1];
    const float* w_dce    = (const float*)d_in[2];
    const float* b_dce    = (const float*)d_in[3];
    const float* w_ch     = (const float*)d_in[4];
    const float* w_shrink = (const float*)d_in[5];
    const float* b_shrink = (const float*)d_in[6];
    const float* w_expand = (const float*)d_in[7];
    const float* b_expand = (const float*)d_in[8];
    const float* w_conv1  = (const float*)d_in[9];
    const float* g_bn1    = (const float*)d_in[10];
    const float* be_bn1   = (const float*)d_in[11];
    const float* w_conv2  = (const float*)d_in[12];
    const float* g_bn2    = (const float*)d_in[13];
    const float* be_bn2   = (const float*)d_in[14];
    const float* w_sc     = (const float*)d_in[15];
    const float* g_bns    = (const float*)d_in[16];
    const float* be_bns   = (const float*)d_in[17];
    float* out = (float*)d_out;

    cudaFuncSetAttribute(k_conv1_mma, cudaFuncAttributeMaxDynamicSharedMemorySize,
                         CONV_SMEM_BYTES);

    k_spatial<<<BATCH*CHAN, 256>>>(x, w_ch);
    k_mod<<<BATCH, 128>>>(dce, w_dce, b_dce, w_shrink, b_shrink, w_expand, b_expand);
    k_transpose<<<256, 256>>>(w_conv2, w_sc);
    k_w1t<<<(9*CHAN*CHAN + 255)/256, 256>>>(w_conv1);   // also zeroes g_stats
    k_xm<<<(BATCH*CHAN*HWSZ/4 + 255)/256, 256>>>(x);
    k_conv1_mma<<<dim3(32, 2, BATCH), 256, CONV_SMEM_BYTES>>>();
    k_prep<<<(BATCH*CHAN*HWSZ/4 + 255)/256, 256>>>(g_bn1, be_bn1);
    k_gemm_mma2<<<dim3(BATCH*HH, 2), 256>>>();
    k_final<<<(BATCH*CHAN*HWSZ/4 + 255)/256, 256>>>(out, g_bn2, be_bn2, g_bns, be_bns);
}

// round 12
// speedup vs baseline: 1.6563x; 1.6100x over previous
#include <cuda_runtime.h>
#include <cuda_fp16.h>
#include <math.h>
#include <stdint.h>

#define BATCH 16
#define CHAN  256
#define CPAIR 128
#define HH    64
#define WW    64
#define HWSZ  4096
#define NHW   65536   // BATCH*HH*WW
#define EPSBN 1e-5f

// ---------------- scratch (device globals; no allocation allowed) ----------------
__device__ float g_t1[BATCH*CHAN*HWSZ];                    // conv1 output (fp32)
__device__ float g_u [BATCH*CHAN*HWSZ];                    // conv2 output (pre-bn2)
__device__ float g_v [BATCH*CHAN*HWSZ];                    // shortcut output (pre-bns)
__device__ __align__(16) uint32_t g_ah [BATCH*CPAIR*HWSZ]; // silu(bn1(t1)) half2 pairs
__device__ __align__(16) uint32_t g_xmh[BATCH*CPAIR*HWSZ]; // x*mod half2 pairs
__device__ __align__(16) uint32_t g_w2t [CPAIR*CHAN];      // w_conv2 half2 [cp][co]
__device__ __align__(16) uint32_t g_wsct[CPAIR*CHAN];      // w_sc   half2 [cp][co]
__device__ __align__(16) uint32_t g_w1h[9*CPAIR*CHAN];     // w_conv1 half2 [tap][cp][co]
__device__ float g_spatial[BATCH*CHAN];
__device__ float g_mod    [BATCH*CHAN];
// [0:C) sum_t1, [C:2C) sq_t1, [2C:3C) sum_u, [3C:4C) sq_u, [4C:5C) sum_v, [5C:6C) sq_v
__device__ float g_stats[6*CHAN];

__device__ __forceinline__ float sigmoidf_(float z) { return 1.f / (1.f + expf(-z)); }
__device__ __forceinline__ float siluf_(float z)    { return z / (1.f + expf(-z)); }

__device__ __forceinline__ uint32_t packh2(float lo, float hi) {
    __half2 h = __floats2half2_rn(lo, hi);
    return *reinterpret_cast<uint32_t*>(&h);
}

// fp16 m16n8k16 MMA with fp32 accumulate
__device__ __forceinline__ void mma_f16(float* c, uint32_t a0, uint32_t a1,
                                        uint32_t a2, uint32_t a3,
                                        uint32_t b0, uint32_t b1) {
    asm volatile(
        "mma.sync.aligned.m16n8k16.row.col.f32.f16.f16.f32 "
        "{%0,%1,%2,%3}, {%4,%5,%6,%7}, {%8,%9}, {%0,%1,%2,%3};"
        : "+f"(c[0]), "+f"(c[1]), "+f"(c[2]), "+f"(c[3])
        : "r"(a0), "r"(a1), "r"(a2), "r"(a3), "r"(b0), "r"(b1));
}

__device__ __forceinline__ uint32_t smem_addr_u32(const void* p) {
    uint32_t a;
    asm("{ .reg .u64 t; cvta.to.shared.u64 t, %1; cvt.u32.u64 %0, t; }"
        : "=r"(a) : "l"(p));
    return a;
}
__device__ __forceinline__ void cp_async4_zfill(uint32_t dst, const void* src, int srcsz) {
    asm volatile("cp.async.ca.shared.global [%0], [%1], 4, %2;"
                 :: "r"(dst), "l"(src), "r"(srcsz));
}
__device__ __forceinline__ void cp_async16(uint32_t dst, const void* src) {
    asm volatile("cp.async.cg.shared.global [%0], [%1], 16;" :: "r"(dst), "l"(src));
}
__device__ __forceinline__ void cp_async_commit_wait() {
    asm volatile("cp.async.commit_group;");
    asm volatile("cp.async.wait_group 0;" ::: "memory");
}

// ---------------- spatial proj via edge-sum decomposition ----------------
__global__ void k_spatial(const float* __restrict__ x, const float* __restrict__ w_ch) {
    int bc = blockIdx.x;
    int c  = bc & (CHAN-1);
    const float* xp = x + (size_t)bc * HWSZ;
    int tid = threadIdx.x;
    int w = tid & 63;

    float T = 0.f, R0 = 0.f, R1 = 0.f, C0 = 0.f, C1 = 0.f;
    for (int i = tid; i < HWSZ; i += 256) {
        int h = i >> 6;
        float v = xp[i];
        T += v;
        if (h == 0)  R0 += v;
        if (h == 63) R1 += v;
        if (w == 0)  C0 += v;
        if (w == 63) C1 += v;
    }
    __shared__ float red[5];
    if (tid < 5) red[tid] = 0.f;
    __syncthreads();
#pragma unroll
    for (int o = 16; o > 0; o >>= 1) {
        T  += __shfl_xor_sync(0xffffffffu, T,  o);
        R0 += __shfl_xor_sync(0xffffffffu, R0, o);
        R1 += __shfl_xor_sync(0xffffffffu, R1, o);
        C0 += __shfl_xor_sync(0xffffffffu, C0, o);
        C1 += __shfl_xor_sync(0xffffffffu, C1, o);
    }
    if ((tid & 31) == 0) {
        atomicAdd(&red[0], T);
        atomicAdd(&red[1], R0);
        atomicAdd(&red[2], R1);
        atomicAdd(&red[3], C0);
        atomicAdd(&red[4], C1);
    }
    __syncthreads();
    if (tid == 0) {
        float Tt = red[0], tR0 = red[1], tR1 = red[2], tC0 = red[3], tC1 = red[4];
        float c00 = xp[0], c0W = xp[63], cH0 = xp[63*64], cHW = xp[4095];
        float acc = 0.f;
#pragma unroll
        for (int t = 0; t < 9; t++) {
            int dy = t / 3 - 1, dx = t % 3 - 1;
            float s = Tt;
            if (dy == 1)  s -= tR0; else if (dy == -1) s -= tR1;
            if (dx == 1)  s -= tC0; else if (dx == -1) s -= tC1;
            if (dy == 1  && dx == 1)  s += c00;
            if (dy == 1  && dx == -1) s += c0W;
            if (dy == -1 && dx == 1)  s += cH0;
            if (dy == -1 && dx == -1) s += cHW;
            acc += w_ch[c*9 + t] * s;
        }
        g_spatial[bc] = acc * (1.f / (float)HWSZ);
    }
}

// ---------------- gate MLP -> g_mod ----------------
__global__ void k_mod(const float* __restrict__ dce, const float* __restrict__ w_dce,
                      const float* __restrict__ b_dce, const float* __restrict__ w_sh,
                      const float* __restrict__ b_sh, const float* __restrict__ w_ex,
                      const float* __restrict__ b_ex) {
    int b = blockIdx.x;
    int t = threadIdx.x;
    __shared__ float pooled[128];
    __shared__ float mbuf[256];
    __shared__ float hbuf[128];

    {
        float s = 0.f;
        const float* dp = dce + (size_t)b * 100 * 128 + t;
        for (int l = 0; l < 100; l++) s += dp[l * 128];
        pooled[t] = s * 0.01f;
    }
    __syncthreads();

    for (int co = t; co < 256; co += 128) {
        float a = b_dce[co];
        const float* wr = w_dce + (size_t)co * 128;
        for (int j = 0; j < 128; j++) a += pooled[j] * wr[j];
        mbuf[co] = a * g_spatial[b*CHAN + co];
    }
    __syncthreads();

    {
        float a = b_sh[t];
        const float* wr = w_sh + (size_t)t * 256;
        for (int i = 0; i < 256; i++) a += mbuf[i] * wr[i];
        hbuf[t] = fmaxf(a, 0.f);
    }
    __syncthreads();

    for (int co = t; co < 256; co += 128) {
        float a = b_ex[co];
        const float* wr = w_ex + (size_t)co * 128;
        for (int i = 0; i < 128; i++) a += hbuf[i] * wr[i];
        g_mod[b*CHAN + co] = sigmoidf_(a);
    }
}

// ---------------- 1x1 weights: [co][ci] -> half2 [cp][co] ----------------
__global__ void k_wk(const float* __restrict__ w2, const float* __restrict__ wsc) {
    int idx = blockIdx.x * blockDim.x + threadIdx.x;
    if (idx >= CPAIR*CHAN) return;
    int cp = idx >> 8, co = idx & 255;
    g_w2t [cp*CHAN + co] = packh2(w2 [(size_t)co*CHAN + 2*cp], w2 [(size_t)co*CHAN + 2*cp+1]);
    g_wsct[cp*CHAN + co] = packh2(wsc[(size_t)co*CHAN + 2*cp], wsc[(size_t)co*CHAN + 2*cp+1]);
}

// ---------------- conv1 weights -> half2 [tap][cp][co]; also zero stats ----------------
__global__ void k_w1t(const float* __restrict__ w1) {
    int idx = blockIdx.x * blockDim.x + threadIdx.x;
    if (idx < 6*CHAN) g_stats[idx] = 0.f;
    if (idx >= 9*CPAIR*CHAN) return;
    int tap = idx >> 15;          // 32768 per tap
    int rem = idx & 32767;
    int cp  = rem >> 8;
    int co  = rem & 255;
    g_w1h[idx] = packh2(w1[(size_t)co*2304 + (2*cp)*9 + tap],
                        w1[(size_t)co*2304 + (2*cp+1)*9 + tap]);
}

// ---------------- xm = half2(x*mod) pair-packed by channel ----------------
__global__ void k_xm(const float* __restrict__ x) {
    int i4 = blockIdx.x * blockDim.x + threadIdx.x;
    size_t base = (size_t)i4 * 4;   // in half2-element space (b, cp, hw)
    if (base >= (size_t)BATCH*CPAIR*HWSZ) return;
    int hw = (int)(base & 4095);
    int cp = (int)((base >> 12) & 127);
    int b  = (int)(base >> 19);
    float mv0 = g_mod[b*CHAN + 2*cp];
    float mv1 = g_mod[b*CHAN + 2*cp + 1];
    const float* x0 = x + ((size_t)b*CHAN + 2*cp)*HWSZ + hw;
    float4 xa = *(const float4*)x0;
    float4 xb = *(const float4*)(x0 + HWSZ);
    uint4 m;
    m.x = packh2(xa.x*mv0, xb.x*mv1);
    m.y = packh2(xa.y*mv0, xb.y*mv1);
    m.z = packh2(xa.z*mv0, xb.z*mv1);
    m.w = packh2(xa.w*mv0, xb.w*mv1);
    *reinterpret_cast<uint4*>(&g_xmh[base]) = m;
}

// ---------------- conv1 via fp16 mma m16n8k16: 9 shifted GEMMs ----------------
// Block tile: M=128 pixels (16 rows x 8 cols), N=128 couts, K-block = 16 ch (8 pairs).
// Warps 4(M) x 2(N): each warp M=32 pixels (4 rows), N=64 couts.
#define PSTR 185                          // half2 words per pair patch row (18*10 + pad)
#define BST  132                          // half2 words per B row (128 couts + pad)
__global__ void __launch_bounds__(256) k_conv1_mma() {
    __shared__ __align__(16) uint32_t s_in[8*PSTR];    // [pair][18x10 patch]
    __shared__ __align__(16) uint32_t s_b [72*BST];    // [tap*8 + pair][co]
    __shared__ float s_sum[128], s_sq[128];

    int b    = blockIdx.z;
    int co0  = blockIdx.y * 128;
    int tile = blockIdx.x;
    int th0  = (tile >> 3) * 16;
    int tw0  = (tile & 7) * 8;

    int tid  = threadIdx.x;
    int warp = tid >> 5;
    int lane = tid & 31;
    int gid  = lane >> 2;
    int tq   = lane & 3;
    int wm   = warp & 3;
    int wn   = warp >> 2;

    if (tid < 128) { s_sum[tid] = 0.f; s_sq[tid] = 0.f; }

    uint32_t s_in_a = smem_addr_u32(s_in);
    uint32_t s_b_a  = smem_addr_u32(s_b);

    float acc[2][8][4];
#pragma unroll
    for (int t = 0; t < 2; t++)
#pragma unroll
        for (int j = 0; j < 8; j++)
#pragma unroll
            for (int k = 0; k < 4; k++) acc[t][j][k] = 0.f;

    for (int cp0 = 0; cp0 < CPAIR; cp0 += 8) {   // 16 iterations of 16 channels
        __syncthreads();

        // ---- input halo patch via cp.async (half2 pairs, zfill OOB) ----
        for (int idx = tid; idx < 8*180; idx += 256) {
            int pr = idx / 180, r = idx - pr*180;
            int iy = r / 10, ix = r - iy*10;
            int gh = th0 + iy - 1, gw = tw0 + ix - 1;
            bool ok = (gh >= 0) && (gh < HH) && (gw >= 0) && (gw < WW);
            const uint32_t* src = g_xmh + (size_t)(b*CPAIR + cp0 + pr)*HWSZ
                                + (ok ? (gh*WW + gw) : 0);
            cp_async4_zfill(s_in_a + (uint32_t)(pr*PSTR + r)*4u, src, ok ? 4 : 0);
        }
        // ---- B: 9 taps x 8 pairs x 128 co = 9216 words = 2304 x 16B ----
        for (int idx4 = tid; idx4 < 2304; idx4 += 256) {
            int w   = idx4 * 4;
            int tap = w >> 10;            // 1024 words per tap (8pr x 128co)
            int rem = w & 1023;
            int pr  = rem >> 7;           // pair 0..7
            int co4 = rem & 127;
            const uint32_t* src = g_w1h + (size_t)tap*32768 + (size_t)(cp0+pr)*256
                                + co0 + co4;
            cp_async16(s_b_a + (uint32_t)((tap*8 + pr)*BST + co4)*4u, src);
        }
        cp_async_commit_wait();
        __syncthreads();

        // ---- mainloop: 9 taps x 16 MMAs (full K=16 per MMA) ----
        for (int tap = 0; tap < 9; tap++) {
            int ky = tap / 3, kx = tap - ky*3;
            uint32_t a0[2], a1[2], a2[2], a3[2];
#pragma unroll
            for (int t = 0; t < 2; t++) {
                int arow = (wm*4 + 2*t + ky)*10 + gid + kx;
                const uint32_t* ap  = s_in + tq*PSTR + arow;        // k pair tq
                const uint32_t* ap4 = s_in + (tq+4)*PSTR + arow;    // k+8 -> pair tq+4
                a0[t] = ap[0];
                a1[t] = ap[10];        // m+8 (next pixel row)
                a2[t] = ap4[0];
                a3[t] = ap4[10];
            }
            const uint32_t* bp  = s_b + (tap*8 + tq)*BST     + wn*64 + gid;
            const uint32_t* bp4 = s_b + (tap*8 + tq + 4)*BST + wn*64 + gid;
#pragma unroll
            for (int j = 0; j < 8; j++) {
                uint32_t b0 = bp[j*8];
                uint32_t b1 = bp4[j*8];
#pragma unroll
                for (int t = 0; t < 2; t++)
                    mma_f16(acc[t][j], a0[t], a1[t], a2[t], a3[t], b0, b1);
            }
        }
    }

    // ---- store + bn1 partial stats (identical mapping to proven round-8) ----
    int px = tw0 + gid;
#pragma unroll
    for (int t = 0; t < 2; t++) {
        int gr = th0 + wm*4 + t*2;
#pragma unroll
        for (int j = 0; j < 8; j++) {
            int col = wn*64 + j*8 + tq*2;
            int co  = co0 + col;
            size_t o0 = (((size_t)b*CHAN + co)*HH + gr)*WW + px;
            float c0v = acc[t][j][0], c1v = acc[t][j][1];
            float c2v = acc[t][j][2], c3v = acc[t][j][3];
            g_t1[o0]             = c0v;
            g_t1[o0 + HWSZ]      = c1v;   // co+1
            g_t1[o0 + WW]        = c2v;   // row+1
            g_t1[o0 + HWSZ + WW] = c3v;

            float s0 = c0v + c2v;
            float s1 = c1v + c3v;
            float q0 = c0v*c0v + c2v*c2v;
            float q1 = c1v*c1v + c3v*c3v;
#pragma unroll
            for (int o = 4; o < 32; o <<= 1) {
                s0 += __shfl_xor_sync(0xffffffffu, s0, o);
                s1 += __shfl_xor_sync(0xffffffffu, s1, o);
                q0 += __shfl_xor_sync(0xffffffffu, q0, o);
                q1 += __shfl_xor_sync(0xffffffffu, q1, o);
            }
            if (gid == 0) {
                atomicAdd(&s_sum[col],     s0);
                atomicAdd(&s_sum[col + 1], s1);
                atomicAdd(&s_sq [col],     q0);
                atomicAdd(&s_sq [col + 1], q1);
            }
        }
    }
    __syncthreads();
    if (tid < 128) {
        atomicAdd(&g_stats[co0 + tid],        s_sum[tid]);
        atomicAdd(&g_stats[CHAN + co0 + tid], s_sq[tid]);
    }
}

// ---------------- prep: g_ah = half2(silu(bn1(t1))) pair-packed ----------------
__global__ void k_prep(const float* __restrict__ g1, const float* __restrict__ be1) {
    int i4 = blockIdx.x * blockDim.x + threadIdx.x;
    size_t base = (size_t)i4 * 4;   // half2-element space
    if (base >= (size_t)BATCH*CPAIR*HWSZ) return;
    int hw = (int)(base & 4095);
    int cp = (int)((base >> 12) & 127);
    int b  = (int)(base >> 19);
    int c0 = 2*cp, c1 = 2*cp + 1;

    float mean0 = g_stats[c0] * (1.f/(float)NHW);
    float var0  = g_stats[CHAN+c0] * (1.f/(float)NHW) - mean0*mean0;
    float sc0   = g1[c0] * rsqrtf(var0 + EPSBN);
    float sh0   = be1[c0] - mean0*sc0;
    float mean1 = g_stats[c1] * (1.f/(float)NHW);
    float var1  = g_stats[CHAN+c1] * (1.f/(float)NHW) - mean1*mean1;
    float sc1   = g1[c1] * rsqrtf(var1 + EPSBN);
    float sh1   = be1[c1] - mean1*sc1;

    const float* t0 = g_t1 + ((size_t)b*CHAN + c0)*HWSZ + hw;
    float4 ta = *(const float4*)t0;
    float4 tb = *(const float4*)(t0 + HWSZ);
    uint4 a;
    a.x = packh2(siluf_(fmaf(ta.x, sc0, sh0)), siluf_(fmaf(tb.x, sc1, sh1)));
    a.y = packh2(siluf_(fmaf(ta.y, sc0, sh0)), siluf_(fmaf(tb.y, sc1, sh1)));
    a.z = packh2(siluf_(fmaf(ta.z, sc0, sh0)), siluf_(fmaf(tb.z, sc1, sh1)));
    a.w = packh2(siluf_(fmaf(ta.w, sc0, sh0)), siluf_(fmaf(tb.w, sc1, sh1)));
    *reinterpret_cast<uint4*>(&g_ah[base]) = a;
}

// ---------------- fused 1x1 GEMMs via fp16 mma, split by path ----------------
//   path 0: u = w2 @ g_ah     path 1: v = wsc @ g_xmh
// grid (B*H = 1024, 2). Block: M=64 pixels (one row), N=256 couts, K-iter = 32 ch.
#define APCH 68    // half2 words per A row (64 px + pad)
#define WPCH 260   // half2 words per W row (256 co + pad)
__global__ void __launch_bounds__(256) k_gemm_mma2() {
    __shared__ __align__(16) uint32_t sA[16*APCH];
    __shared__ __align__(16) uint32_t sW[16*WPCH];
    __shared__ float s_s[CHAN], s_q[CHAN];

    int bh   = blockIdx.x;
    int b    = bh >> 6;
    int h    = bh & 63;
    int path = blockIdx.y;          // 0 = u, 1 = v
    int tid  = threadIdx.x;
    int warp = tid >> 5;
    int lane = tid & 31;
    int gid  = lane >> 2;
    int tq   = lane & 3;
    int mt   = (warp & 1) * 32;
    int n0   = (warp >> 1) * 64;

    s_s[tid] = 0.f;
    s_q[tid] = 0.f;

    float acc[2][8][4];
#pragma unroll
    for (int t = 0; t < 2; t++)
#pragma unroll
        for (int j = 0; j < 8; j++)
#pragma unroll
            for (int k = 0; k < 4; k++) acc[t][j][k] = 0.f;

    const uint32_t* wsrc = path ? g_wsct : g_w2t;
    const uint32_t* asrc = path ? g_xmh  : g_ah;
    size_t rowb = ((size_t)b*CPAIR)*HWSZ + h*WW;   // + cp*HWSZ + p

    for (int cp0 = 0; cp0 < CPAIR; cp0 += 16) {    // 8 iterations of 32 channels
        __syncthreads();
        // A tile: 16 pairs x 64 px (uint4 copies)
        for (int idx4 = tid; idx4 < 256; idx4 += 256) {
            // fallthrough below handles all via strided loop
        }
        for (int idx4 = tid; idx4 < 256; idx4 += 256) { (void)idx4; }
        for (int idx4 = tid; idx4 < 256; idx4 += 256) { (void)idx4; }
        for (int idx4 = tid; idx4 < 256; idx4 += 256) {
            int pr = idx4 >> 4, p4 = idx4 & 15;
            *reinterpret_cast<uint4*>(sA + pr*APCH + p4*4) =
                *reinterpret_cast<const uint4*>(asrc + rowb + (size_t)(cp0+pr)*HWSZ + p4*4);
        }
        // W tile: 16 pairs x 256 co (uint4 copies)
        for (int idx4 = tid; idx4 < 1024; idx4 += 256) {
            int pr = idx4 >> 6, co4 = idx4 & 63;
            *reinterpret_cast<uint4*>(sW + pr*WPCH + co4*4) =
                *reinterpret_cast<const uint4*>(wsrc + (size_t)(cp0+pr)*CHAN + co4*4);
        }
        __syncthreads();

#pragma unroll
        for (int ks = 0; ks < 2; ks++) {
            uint32_t a0[2], a1[2], a2[2], a3[2];
#pragma unroll
            for (int t = 0; t < 2; t++) {
                const uint32_t* ap  = sA + (ks*8 + tq)*APCH     + mt + t*16 + gid;
                const uint32_t* ap4 = sA + (ks*8 + tq + 4)*APCH + mt + t*16 + gid;
                a0[t] = ap[0];
                a1[t] = ap[8];        // m+8
                a2[t] = ap4[0];       // k+8
                a3[t] = ap4[8];
            }
            const uint32_t* bp  = sW + (ks*8 + tq)*WPCH     + n0 + gid;
            const uint32_t* bp4 = sW + (ks*8 + tq + 4)*WPCH + n0 + gid;
#pragma unroll
            for (int j = 0; j < 8; j++) {
                uint32_t b0 = bp[j*8];
                uint32_t b1 = bp4[j*8];
#pragma unroll
                for (int t = 0; t < 2; t++)
                    mma_f16(acc[t][j], a0[t], a1[t], a2[t], a3[t], b0, b1);
            }
        }
    }

    float* gout = path ? g_v : g_u;
#pragma unroll
    for (int t = 0; t < 2; t++) {
        int p = mt + t*16 + gid;
#pragma unroll
        for (int j = 0; j < 8; j++) {
            int co = n0 + j*8 + tq*2;
            size_t o0 = (((size_t)b*CHAN + co)*HH + h)*WW + p;
            float c0v = acc[t][j][0], c1v = acc[t][j][1];
            float c2v = acc[t][j][2], c3v = acc[t][j][3];
            gout[o0]            = c0v;
            gout[o0 + HWSZ]     = c1v;   // co+1
            gout[o0 + 8]        = c2v;   // p+8
            gout[o0 + HWSZ + 8] = c3v;

            float s0 = c0v + c2v;
            float s1 = c1v + c3v;
            float q0 = c0v*c0v + c2v*c2v;
            float q1 = c1v*c1v + c3v*c3v;
#pragma unroll
            for (int o = 4; o < 32; o <<= 1) {
                s0 += __shfl_xor_sync(0xffffffffu, s0, o);
                s1 += __shfl_xor_sync(0xffffffffu, s1, o);
                q0 += __shfl_xor_sync(0xffffffffu, q0, o);
                q1 += __shfl_xor_sync(0xffffffffu, q1, o);
            }
            if (gid == 0) {
                atomicAdd(&s_s[co],     s0);
                atomicAdd(&s_s[co + 1], s1);
                atomicAdd(&s_q[co],     q0);
                atomicAdd(&s_q[co + 1], q1);
            }
        }
    }
    __syncthreads();
    {
        int soff = 2*CHAN + 2*CHAN*path;
        atomicAdd(&g_stats[soff + tid],        s_s[tid]);
        atomicAdd(&g_stats[soff + CHAN + tid], s_q[tid]);
    }
}

// ---------------- final: out = silu(bn2(u) + bns(v)) ----------------
__global__ void k_final(float* __restrict__ out,
                        const float* __restrict__ g2, const float* __restrict__ be2,
                        const float* __restrict__ gs, const float* __restrict__ bes) {
    int i4 = blockIdx.x * blockDim.x + threadIdx.x;
    size_t base = (size_t)i4 * 4;
    if (base >= (size_t)BATCH*CHAN*HWSZ) return;
    int c = (int)((base >> 12) & 255);

    float mu = g_stats[2*CHAN + c] * (1.f / (float)NHW);
    float vu = g_stats[3*CHAN + c] * (1.f / (float)NHW) - mu*mu;
    float su = g2[c] * rsqrtf(vu + EPSBN);
    float bu = be2[c] - mu * su;

    float mv = g_stats[4*CHAN + c] * (1.f / (float)NHW);
    float vv = g_stats[5*CHAN + c] * (1.f / (float)NHW) - mv*mv;
    float sv = gs[c] * rsqrtf(vv + EPSBN);
    float bv = bes[c] - mv * sv;

    float4 u = *(const float4*)&g_u[base];
    float4 v = *(const float4*)&g_v[base];
    float4 o;
    {
        float z;
        z = fmaf(u.x, su, bu) + fmaf(v.x, sv, bv); o.x = siluf_(z);
        z = fmaf(u.y, su, bu) + fmaf(v.y, sv, bv); o.y = siluf_(z);
        z = fmaf(u.z, su, bu) + fmaf(v.z, sv, bv); o.z = siluf_(z);
        z = fmaf(u.w, su, bu) + fmaf(v.w, sv, bv); o.w = siluf_(z);
    }
    *(float4*)&out[base] = o;
}

// ---------------- launch ----------------
extern "C" void kernel_launch(void* const* d_in, const int* in_sizes, int n_in,
                              void* d_out, int out_size) {
    const float* x        = (const float*)d_in[0];
    const float* dce      = (const float*)d_in[1];
    const float* w_dce    = (const float*)d_in[2];
    const float* b_dce    = (const float*)d_in[3];
    const float* w_ch     = (const float*)d_in[4];
    const float* w_shrink = (const float*)d_in[5];
    const float* b_shrink = (const float*)d_in[6];
    const float* w_expand = (const float*)d_in[7];
    const float* b_expand = (const float*)d_in[8];
    const float* w_conv1  = (const float*)d_in[9];
    const float* g_bn1    = (const float*)d_in[10];
    const float* be_bn1   = (const float*)d_in[11];
    const float* w_conv2  = (const float*)d_in[12];
    const float* g_bn2    = (const float*)d_in[13];
    const float* be_bn2   = (const float*)d_in[14];
    const float* w_sc     = (const float*)d_in[15];
    const float* g_bns    = (const float*)d_in[16];
    const float* be_bns   = (const float*)d_in[17];
    float* out = (float*)d_out;

    k_spatial<<<BATCH*CHAN, 256>>>(x, w_ch);
    k_mod<<<BATCH, 128>>>(dce, w_dce, b_dce, w_shrink, b_shrink, w_expand, b_expand);
    k_wk<<<(CPAIR*CHAN + 255)/256, 256>>>(w_conv2, w_sc);
    k_w1t<<<(9*CPAIR*CHAN + 255)/256, 256>>>(w_conv1);   // also zeroes g_stats
    k_xm<<<(BATCH*CPAIR*HWSZ/4 + 255)/256, 256>>>(x);
    k_conv1_mma<<<dim3(32, 2, BATCH), 256>>>();
    k_prep<<<(BATCH*CPAIR*HWSZ/4 + 255)/256, 256>>>(g_bn1, be_bn1);
    k_gemm_mma2<<<dim3(BATCH*HH, 2), 256>>>();
    k_final<<<(BATCH*CHAN*HWSZ/4 + 255)/256, 256>>>(out, g_bn2, be_bn2, g_bns, be_bns);
}

// round 13
// speedup vs baseline: 1.7019x; 1.0275x over previous
#include <cuda_runtime.h>
#include <cuda_fp16.h>
#include <math.h>
#include <stdint.h>

#define BATCH 16
#define CHAN  256
#define CPAIR 128
#define HH    64
#define WW    64
#define HWSZ  4096
#define NHW   65536   // BATCH*HH*WW
#define EPSBN 1e-5f

// ---------------- scratch (device globals; no allocation allowed) ----------------
// uint2 element = { half2(ch 2cp, 2cp+1), half2(ch 2cp+8, 2cp+9) } with cp = kblk*8 + p4
__device__ float g_t1[BATCH*CHAN*HWSZ];                   // conv1 output (fp32)
__device__ float g_u [BATCH*CHAN*HWSZ];                   // conv2 output (pre-bn2)
__device__ float g_v [BATCH*CHAN*HWSZ];                   // shortcut output (pre-bns)
__device__ __align__(16) uint2 g_a2 [BATCH*64*HWSZ];      // silu(bn1(t1)) interleaved
__device__ __align__(16) uint2 g_xm2[BATCH*64*HWSZ];      // x*mod interleaved
__device__ __align__(16) uint2 g_w2p [16*4*CHAN];         // w_conv2 [kblk][p4][co]
__device__ __align__(16) uint2 g_wscp[16*4*CHAN];         // w_sc    [kblk][p4][co]
__device__ __align__(16) uint2 g_w1p[9*16*4*CHAN];        // w_conv1 [tap][kblk][p4][co]
__device__ float g_spatial[BATCH*CHAN];
__device__ float g_mod    [BATCH*CHAN];
// [0:C) sum_t1, [C:2C) sq_t1, [2C:3C) sum_u, [3C:4C) sq_u, [4C:5C) sum_v, [5C:6C) sq_v
__device__ float g_stats[6*CHAN];

__device__ __forceinline__ float sigmoidf_(float z) { return 1.f / (1.f + expf(-z)); }
__device__ __forceinline__ float siluf_(float z)    { return z / (1.f + expf(-z)); }

__device__ __forceinline__ uint32_t packh2(float lo, float hi) {
    __half2 h = __floats2half2_rn(lo, hi);
    return *reinterpret_cast<uint32_t*>(&h);
}

// fp16 m16n8k16 MMA with fp32 accumulate
__device__ __forceinline__ void mma_f16(float* c, uint32_t a0, uint32_t a1,
                                        uint32_t a2, uint32_t a3,
                                        uint32_t b0, uint32_t b1) {
    asm volatile(
        "mma.sync.aligned.m16n8k16.row.col.f32.f16.f16.f32 "
        "{%0,%1,%2,%3}, {%4,%5,%6,%7}, {%8,%9}, {%0,%1,%2,%3};"
        : "+f"(c[0]), "+f"(c[1]), "+f"(c[2]), "+f"(c[3])
        : "r"(a0), "r"(a1), "r"(a2), "r"(a3), "r"(b0), "r"(b1));
}

__device__ __forceinline__ uint32_t smem_addr_u32(const void* p) {
    uint32_t a;
    asm("{ .reg .u64 t; cvta.to.shared.u64 t, %1; cvt.u32.u64 %0, t; }"
        : "=r"(a) : "l"(p));
    return a;
}
__device__ __forceinline__ void cp_async8_zfill(uint32_t dst, const void* src, int srcsz) {
    asm volatile("cp.async.ca.shared.global [%0], [%1], 8, %2;"
                 :: "r"(dst), "l"(src), "r"(srcsz));
}
__device__ __forceinline__ void cp_async16(uint32_t dst, const void* src) {
    asm volatile("cp.async.cg.shared.global [%0], [%1], 16;" :: "r"(dst), "l"(src));
}
__device__ __forceinline__ void cp_async_commit_wait() {
    asm volatile("cp.async.commit_group;");
    asm volatile("cp.async.wait_group 0;" ::: "memory");
}

// ---------------- spatial proj via edge-sum decomposition ----------------
__global__ void k_spatial(const float* __restrict__ x, const float* __restrict__ w_ch) {
    int bc = blockIdx.x;
    int c  = bc & (CHAN-1);
    const float* xp = x + (size_t)bc * HWSZ;
    int tid = threadIdx.x;
    int w = tid & 63;

    float T = 0.f, R0 = 0.f, R1 = 0.f, C0 = 0.f, C1 = 0.f;
    for (int i = tid; i < HWSZ; i += 256) {
        int h = i >> 6;
        float v = xp[i];
        T += v;
        if (h == 0)  R0 += v;
        if (h == 63) R1 += v;
        if (w == 0)  C0 += v;
        if (w == 63) C1 += v;
    }
    __shared__ float red[5];
    if (tid < 5) red[tid] = 0.f;
    __syncthreads();
#pragma unroll
    for (int o = 16; o > 0; o >>= 1) {
        T  += __shfl_xor_sync(0xffffffffu, T,  o);
        R0 += __shfl_xor_sync(0xffffffffu, R0, o);
        R1 += __shfl_xor_sync(0xffffffffu, R1, o);
        C0 += __shfl_xor_sync(0xffffffffu, C0, o);
        C1 += __shfl_xor_sync(0xffffffffu, C1, o);
    }
    if ((tid & 31) == 0) {
        atomicAdd(&red[0], T);
        atomicAdd(&red[1], R0);
        atomicAdd(&red[2], R1);
        atomicAdd(&red[3], C0);
        atomicAdd(&red[4], C1);
    }
    __syncthreads();
    if (tid == 0) {
        float Tt = red[0], tR0 = red[1], tR1 = red[2], tC0 = red[3], tC1 = red[4];
        float c00 = xp[0], c0W = xp[63], cH0 = xp[63*64], cHW = xp[4095];
        float acc = 0.f;
#pragma unroll
        for (int t = 0; t < 9; t++) {
            int dy = t / 3 - 1, dx = t % 3 - 1;
            float s = Tt;
            if (dy == 1)  s -= tR0; else if (dy == -1) s -= tR1;
            if (dx == 1)  s -= tC0; else if (dx == -1) s -= tC1;
            if (dy == 1  && dx == 1)  s += c00;
            if (dy == 1  && dx == -1) s += c0W;
            if (dy == -1 && dx == 1)  s += cH0;
            if (dy == -1 && dx == -1) s += cHW;
            acc += w_ch[c*9 + t] * s;
        }
        g_spatial[bc] = acc * (1.f / (float)HWSZ);
    }
}

// ---------------- gate MLP -> g_mod ----------------
__global__ void k_mod(const float* __restrict__ dce, const float* __restrict__ w_dce,
                      const float* __restrict__ b_dce, const float* __restrict__ w_sh,
                      const float* __restrict__ b_sh, const float* __restrict__ w_ex,
                      const float* __restrict__ b_ex) {
    int b = blockIdx.x;
    int t = threadIdx.x;
    __shared__ float pooled[128];
    __shared__ float mbuf[256];
    __shared__ float hbuf[128];

    {
        float s = 0.f;
        const float* dp = dce + (size_t)b * 100 * 128 + t;
        for (int l = 0; l < 100; l++) s += dp[l * 128];
        pooled[t] = s * 0.01f;
    }
    __syncthreads();

    for (int co = t; co < 256; co += 128) {
        float a = b_dce[co];
        const float* wr = w_dce + (size_t)co * 128;
        for (int j = 0; j < 128; j++) a += pooled[j] * wr[j];
        mbuf[co] = a * g_spatial[b*CHAN + co];
    }
    __syncthreads();

    {
        float a = b_sh[t];
        const float* wr = w_sh + (size_t)t * 256;
        for (int i = 0; i < 256; i++) a += mbuf[i] * wr[i];
        hbuf[t] = fmaxf(a, 0.f);
    }
    __syncthreads();

    for (int co = t; co < 256; co += 128) {
        float a = b_ex[co];
        const float* wr = w_ex + (size_t)co * 128;
        for (int i = 0; i < 128; i++) a += hbuf[i] * wr[i];
        g_mod[b*CHAN + co] = sigmoidf_(a);
    }
}

// ---------------- 1x1 weights -> interleaved uint2 [kblk][p4][co] ----------------
__global__ void k_wk(const float* __restrict__ w2, const float* __restrict__ wsc) {
    int idx = blockIdx.x * blockDim.x + threadIdx.x;
    if (idx >= 16*4*CHAN) return;
    int co   = idx & 255;
    int p4   = (idx >> 8) & 3;
    int kblk = idx >> 10;
    int cA = 2*(kblk*8 + p4);          // lo pair channels cA, cA+1; hi pair cA+8, cA+9
    const float* r2 = w2  + (size_t)co*CHAN;
    const float* rs = wsc + (size_t)co*CHAN;
    g_w2p [idx] = make_uint2(packh2(r2[cA], r2[cA+1]), packh2(r2[cA+8], r2[cA+9]));
    g_wscp[idx] = make_uint2(packh2(rs[cA], rs[cA+1]), packh2(rs[cA+8], rs[cA+9]));
}

// ---------------- conv1 weights -> uint2 [tap][kblk][p4][co]; also zero stats ------------
__global__ void k_w1t(const float* __restrict__ w1) {
    int idx = blockIdx.x * blockDim.x + threadIdx.x;
    if (idx < 6*CHAN) g_stats[idx] = 0.f;
    if (idx >= 9*16*4*CHAN) return;
    int co   = idx & 255;
    int p4   = (idx >> 8) & 3;
    int kblk = (idx >> 10) & 15;
    int tap  = idx >> 14;
    int cA = 2*(kblk*8 + p4);
    const float* wr = w1 + (size_t)co*2304;
    g_w1p[idx] = make_uint2(
        packh2(wr[cA*9 + tap],     wr[(cA+1)*9 + tap]),
        packh2(wr[(cA+8)*9 + tap], wr[(cA+9)*9 + tap]));
}

// ---------------- xm = interleaved half2(x*mod) ----------------
__global__ void k_xm(const float* __restrict__ x) {
    int i4 = blockIdx.x * blockDim.x + threadIdx.x;
    size_t base = (size_t)i4 * 4;       // uint2-element index
    if (base >= (size_t)BATCH*64*HWSZ) return;
    int hw   = (int)(base & 4095);
    int p4   = (int)((base >> 12) & 3);
    int kblk = (int)((base >> 14) & 15);
    int b    = (int)(base >> 18);
    int cA = 2*(kblk*8 + p4);
    float m0 = g_mod[b*CHAN + cA],   m1 = g_mod[b*CHAN + cA+1];
    float m2 = g_mod[b*CHAN + cA+8], m3 = g_mod[b*CHAN + cA+9];
    const float* x0 = x + ((size_t)b*CHAN + cA)*HWSZ + hw;
    float4 a0 = *(const float4*)x0;
    float4 a1 = *(const float4*)(x0 + HWSZ);
    float4 b0 = *(const float4*)(x0 + 8*HWSZ);
    float4 b1 = *(const float4*)(x0 + 9*HWSZ);
    uint4 o0, o1;
    o0.x = packh2(a0.x*m0, a1.x*m1); o0.y = packh2(b0.x*m2, b1.x*m3);
    o0.z = packh2(a0.y*m0, a1.y*m1); o0.w = packh2(b0.y*m2, b1.y*m3);
    o1.x = packh2(a0.z*m0, a1.z*m1); o1.y = packh2(b0.z*m2, b1.z*m3);
    o1.z = packh2(a0.w*m0, a1.w*m1); o1.w = packh2(b0.w*m2, b1.w*m3);
    uint4* dst = reinterpret_cast<uint4*>(&g_xm2[base]);
    dst[0] = o0;
    dst[1] = o1;
}

// ---------------- conv1 via fp16 mma m16n8k16, pair-interleaved smem ----------------
// Block tile: M=128 pixels (16 rows x 8 cols), N=128 couts, K-stage = 16 ch (kblk).
// Warps 4(M) x 2(N). All fragment loads are LDS.64, conflict-free pitches.
#define PST2 200                          // uint2 per p4 patch row (18*10=180 + pad), %32==8
#define BST2 136                          // uint2 per B row (128 co + pad), %32==8
__global__ void __launch_bounds__(256) k_conv1_mma() {
    __shared__ __align__(16) uint2 s_in[4*PST2];    // [p4][18x10 patch]
    __shared__ __align__(16) uint2 s_b [36*BST2];   // [tap*4 + p4][co]
    __shared__ float s_sum[128], s_sq[128];

    int b    = blockIdx.z;
    int co0  = blockIdx.y * 128;
    int tile = blockIdx.x;
    int th0  = (tile >> 3) * 16;
    int tw0  = (tile & 7) * 8;

    int tid  = threadIdx.x;
    int warp = tid >> 5;
    int lane = tid & 31;
    int gid  = lane >> 2;
    int tq   = lane & 3;
    int wm   = warp & 3;
    int wn   = warp >> 2;

    if (tid < 128) { s_sum[tid] = 0.f; s_sq[tid] = 0.f; }

    uint32_t s_in_a = smem_addr_u32(s_in);
    uint32_t s_b_a  = smem_addr_u32(s_b);

    float acc[2][8][4];
#pragma unroll
    for (int t = 0; t < 2; t++)
#pragma unroll
        for (int j = 0; j < 8; j++)
#pragma unroll
            for (int k = 0; k < 4; k++) acc[t][j][k] = 0.f;

    for (int kblk = 0; kblk < 16; kblk++) {      // 16 stages of 16 channels
        __syncthreads();

        // ---- A halo patch: 4 p4-rows x 180, 8B cp.async (zfill OOB) ----
        for (int idx = tid; idx < 4*180; idx += 256) {
            int p4 = idx / 180, r = idx - p4*180;
            int iy = r / 10, ix = r - iy*10;
            int gh = th0 + iy - 1, gw = tw0 + ix - 1;
            bool ok = (gh >= 0) && (gh < HH) && (gw >= 0) && (gw < WW);
            const uint2* src = g_xm2 + (size_t)((b*16 + kblk)*4 + p4)*HWSZ
                             + (ok ? (gh*WW + gw) : 0);
            cp_async8_zfill(s_in_a + (uint32_t)(p4*PST2 + r)*8u, src, ok ? 8 : 0);
        }
        // ---- B: 9 taps x 4 p4 x 128 co uint2 = 2304 x 16B cp.async ----
        for (int idx2 = tid; idx2 < 2304; idx2 += 256) {
            int lin = idx2 * 2;               // uint2 units
            int tap = lin >> 9;               // 512 uint2 per tap
            int rem = lin & 511;
            int p4  = rem >> 7;
            int coU = rem & 127;              // even
            const uint2* src = g_w1p + (size_t)((tap*16 + kblk)*4 + p4)*256
                             + co0 + coU;
            cp_async16(s_b_a + (uint32_t)((tap*4 + p4)*BST2 + coU)*8u, src);
        }
        cp_async_commit_wait();
        __syncthreads();

        // ---- mainloop: 9 taps x 16 MMAs, all LDS.64 fragments ----
        for (int tap = 0; tap < 9; tap++) {
            int ky = tap / 3, kx = tap - ky*3;
            uint2 aL[2], aH[2];
#pragma unroll
            for (int t = 0; t < 2; t++) {
                int arow = (wm*4 + 2*t + ky)*10 + gid + kx;
                const uint2* ap = s_in + tq*PST2 + arow;
                aL[t] = ap[0];     // {a0 (k-lo), a2 (k-hi)} at pixel row
                aH[t] = ap[10];    // {a1, a3} at pixel row+8
            }
            const uint2* bp = s_b + (tap*4 + tq)*BST2 + wn*64 + gid;
#pragma unroll
            for (int j = 0; j < 8; j++) {
                uint2 bb = bp[j*8];
#pragma unroll
                for (int t = 0; t < 2; t++)
                    mma_f16(acc[t][j], aL[t].x, aH[t].x, aL[t].y, aH[t].y, bb.x, bb.y);
            }
        }
    }

    // ---- store + bn1 partial stats (identical mapping to proven round-12) ----
    int px = tw0 + gid;
#pragma unroll
    for (int t = 0; t < 2; t++) {
        int gr = th0 + wm*4 + t*2;
#pragma unroll
        for (int j = 0; j < 8; j++) {
            int col = wn*64 + j*8 + tq*2;
            int co  = co0 + col;
            size_t o0 = (((size_t)b*CHAN + co)*HH + gr)*WW + px;
            float c0v = acc[t][j][0], c1v = acc[t][j][1];
            float c2v = acc[t][j][2], c3v = acc[t][j][3];
            g_t1[o0]             = c0v;
            g_t1[o0 + HWSZ]      = c1v;   // co+1
            g_t1[o0 + WW]        = c2v;   // row+1
            g_t1[o0 + HWSZ + WW] = c3v;

            float s0 = c0v + c2v;
            float s1 = c1v + c3v;
            float q0 = c0v*c0v + c2v*c2v;
            float q1 = c1v*c1v + c3v*c3v;
#pragma unroll
            for (int o = 4; o < 32; o <<= 1) {
                s0 += __shfl_xor_sync(0xffffffffu, s0, o);
                s1 += __shfl_xor_sync(0xffffffffu, s1, o);
                q0 += __shfl_xor_sync(0xffffffffu, q0, o);
                q1 += __shfl_xor_sync(0xffffffffu, q1, o);
            }
            if (gid == 0) {
                atomicAdd(&s_sum[col],     s0);
                atomicAdd(&s_sum[col + 1], s1);
                atomicAdd(&s_sq [col],     q0);
                atomicAdd(&s_sq [col + 1], q1);
            }
        }
    }
    __syncthreads();
    if (tid < 128) {
        atomicAdd(&g_stats[co0 + tid],        s_sum[tid]);
        atomicAdd(&g_stats[CHAN + co0 + tid], s_sq[tid]);
    }
}

// ---------------- prep: g_a2 = interleaved half2(silu(bn1(t1))) ----------------
__global__ void k_prep(const float* __restrict__ g1, const float* __restrict__ be1) {
    int i4 = blockIdx.x * blockDim.x + threadIdx.x;
    size_t base = (size_t)i4 * 4;       // uint2-element index
    if (base >= (size_t)BATCH*64*HWSZ) return;
    int hw   = (int)(base & 4095);
    int p4   = (int)((base >> 12) & 3);
    int kblk = (int)((base >> 14) & 15);
    int b    = (int)(base >> 18);
    int cA = 2*(kblk*8 + p4);

    float sc[4], sh[4];
    int cs[4] = {cA, cA+1, cA+8, cA+9};
#pragma unroll
    for (int i = 0; i < 4; i++) {
        int c = cs[i];
        float mean = g_stats[c] * (1.f/(float)NHW);
        float var  = g_stats[CHAN+c] * (1.f/(float)NHW) - mean*mean;
        sc[i] = g1[c] * rsqrtf(var + EPSBN);
        sh[i] = be1[c] - mean*sc[i];
    }
    const float* t0 = g_t1 + ((size_t)b*CHAN + cA)*HWSZ + hw;
    float4 a0 = *(const float4*)t0;
    float4 a1 = *(const float4*)(t0 + HWSZ);
    float4 b0 = *(const float4*)(t0 + 8*HWSZ);
    float4 b1 = *(const float4*)(t0 + 9*HWSZ);
    uint4 o0, o1;
    o0.x = packh2(siluf_(fmaf(a0.x, sc[0], sh[0])), siluf_(fmaf(a1.x, sc[1], sh[1])));
    o0.y = packh2(siluf_(fmaf(b0.x, sc[2], sh[2])), siluf_(fmaf(b1.x, sc[3], sh[3])));
    o0.z = packh2(siluf_(fmaf(a0.y, sc[0], sh[0])), siluf_(fmaf(a1.y, sc[1], sh[1])));
    o0.w = packh2(siluf_(fmaf(b0.y, sc[2], sh[2])), siluf_(fmaf(b1.y, sc[3], sh[3])));
    o1.x = packh2(siluf_(fmaf(a0.z, sc[0], sh[0])), siluf_(fmaf(a1.z, sc[1], sh[1])));
    o1.y = packh2(siluf_(fmaf(b0.z, sc[2], sh[2])), siluf_(fmaf(b1.z, sc[3], sh[3])));
    o1.z = packh2(siluf_(fmaf(a0.w, sc[0], sh[0])), siluf_(fmaf(a1.w, sc[1], sh[1])));
    o1.w = packh2(siluf_(fmaf(b0.w, sc[2], sh[2])), siluf_(fmaf(b1.w, sc[3], sh[3])));
    uint4* dst = reinterpret_cast<uint4*>(&g_a2[base]);
    dst[0] = o0;
    dst[1] = o1;
}

// ---------------- fused 1x1 GEMMs via fp16 mma, pair-interleaved ----------------
//   path 0: u = w2 @ g_a2     path 1: v = wsc @ g_xm2
// grid (B*H = 1024, 2). Block: M=64 pixels (one row), N=256 couts, K-iter = 2 kblks.
#define APC2 72    // uint2 per A row (64 px + pad), %32==8
#define WPC2 264   // uint2 per W row (256 co + pad), %32==8
__global__ void __launch_bounds__(256) k_gemm_mma2() {
    __shared__ __align__(16) uint2 sA[8*APC2];
    __shared__ __align__(16) uint2 sW[8*WPC2];
    __shared__ float s_s[CHAN], s_q[CHAN];

    int bh   = blockIdx.x;
    int b    = bh >> 6;
    int h    = bh & 63;
    int path = blockIdx.y;          // 0 = u, 1 = v
    int tid  = threadIdx.x;
    int warp = tid >> 5;
    int lane = tid & 31;
    int gid  = lane >> 2;
    int tq   = lane & 3;
    int mt   = (warp & 1) * 32;
    int n0   = (warp >> 1) * 64;

    s_s[tid] = 0.f;
    s_q[tid] = 0.f;

    float acc[2][8][4];
#pragma unroll
    for (int t = 0; t < 2; t++)
#pragma unroll
        for (int j = 0; j < 8; j++)
#pragma unroll
            for (int k = 0; k < 4; k++) acc[t][j][k] = 0.f;

    const uint2* wsrc = path ? g_wscp : g_w2p;
    const uint2* asrc = path ? g_xm2  : g_a2;
    size_t arow0 = (size_t)b*64*HWSZ + h*WW;   // + (kblk*4+p4)*HWSZ + px

    for (int kb0 = 0; kb0 < 16; kb0 += 2) {    // 8 iterations of 32 channels
        __syncthreads();
        // A tile: 8 rows (2 kblk x 4 p4) x 64 px
        for (int idx4 = tid; idx4 < 256; idx4 += 256) {
            int row = idx4 >> 5, px2 = (idx4 & 31) * 2;
            *reinterpret_cast<uint4*>(sA + row*APC2 + px2) =
                *reinterpret_cast<const uint4*>(asrc + arow0 + (size_t)(kb0*4 + row)*HWSZ + px2);
        }
        // W tile: 8 rows x 256 co
        for (int idx4 = tid; idx4 < 1024; idx4 += 256) {
            int row = idx4 >> 7, co2 = (idx4 & 127) * 2;
            *reinterpret_cast<uint4*>(sW + row*WPC2 + co2) =
                *reinterpret_cast<const uint4*>(wsrc + (size_t)(kb0*4 + row)*256 + co2);
        }
        __syncthreads();

#pragma unroll
        for (int grp = 0; grp < 2; grp++) {
            uint2 aL[2], aH[2];
#pragma unroll
            for (int t = 0; t < 2; t++) {
                const uint2* ap = sA + (grp*4 + tq)*APC2 + mt + t*16 + gid;
                aL[t] = ap[0];
                aH[t] = ap[8];     // m+8
            }
            const uint2* bp = sW + (grp*4 + tq)*WPC2 + n0 + gid;
#pragma unroll
            for (int j = 0; j < 8; j++) {
                uint2 bb = bp[j*8];
#pragma unroll
                for (int t = 0; t < 2; t++)
                    mma_f16(acc[t][j], aL[t].x, aH[t].x, aL[t].y, aH[t].y, bb.x, bb.y);
            }
        }
    }

    float* gout = path ? g_v : g_u;
#pragma unroll
    for (int t = 0; t < 2; t++) {
        int p = mt + t*16 + gid;
#pragma unroll
        for (int j = 0; j < 8; j++) {
            int co = n0 + j*8 + tq*2;
            size_t o0 = (((size_t)b*CHAN + co)*HH + h)*WW + p;
            float c0v = acc[t][j][0], c1v = acc[t][j][1];
            float c2v = acc[t][j][2], c3v = acc[t][j][3];
            gout[o0]            = c0v;
            gout[o0 + HWSZ]     = c1v;   // co+1
            gout[o0 + 8]        = c2v;   // p+8
            gout[o0 + HWSZ + 8] = c3v;

            float s0 = c0v + c2v;
            float s1 = c1v + c3v;
            float q0 = c0v*c0v + c2v*c2v;
            float q1 = c1v*c1v + c3v*c3v;
#pragma unroll
            for (int o = 4; o < 32; o <<= 1) {
                s0 += __shfl_xor_sync(0xffffffffu, s0, o);
                s1 += __shfl_xor_sync(0xffffffffu, s1, o);
                q0 += __shfl_xor_sync(0xffffffffu, q0, o);
                q1 += __shfl_xor_sync(0xffffffffu, q1, o);
            }
            if (gid == 0) {
                atomicAdd(&s_s[co],     s0);
                atomicAdd(&s_s[co + 1], s1);
                atomicAdd(&s_q[co],     q0);
                atomicAdd(&s_q[co + 1], q1);
            }
        }
    }
    __syncthreads();
    {
        int soff = 2*CHAN + 2*CHAN*path;
        atomicAdd(&g_stats[soff + tid],        s_s[tid]);
        atomicAdd(&g_stats[soff + CHAN + tid], s_q[tid]);
    }
}

// ---------------- final: out = silu(bn2(u) + bns(v)) ----------------
__global__ void k_final(float* __restrict__ out,
                        const float* __restrict__ g2, const float* __restrict__ be2,
                        const float* __restrict__ gs, const float* __restrict__ bes) {
    int i4 = blockIdx.x * blockDim.x + threadIdx.x;
    size_t base = (size_t)i4 * 4;
    if (base >= (size_t)BATCH*CHAN*HWSZ) return;
    int c = (int)((base >> 12) & 255);

    float mu = g_stats[2*CHAN + c] * (1.f / (float)NHW);
    float vu = g_stats[3*CHAN + c] * (1.f / (float)NHW) - mu*mu;
    float su = g2[c] * rsqrtf(vu + EPSBN);
    float bu = be2[c] - mu * su;

    float mv = g_stats[4*CHAN + c] * (1.f / (float)NHW);
    float vv = g_stats[5*CHAN + c] * (1.f / (float)NHW) - mv*mv;
    float sv = gs[c] * rsqrtf(vv + EPSBN);
    float bv = bes[c] - mv * sv;

    float4 u = *(const float4*)&g_u[base];
    float4 v = *(const float4*)&g_v[base];
    float4 o;
    {
        float z;
        z = fmaf(u.x, su, bu) + fmaf(v.x, sv, bv); o.x = siluf_(z);
        z = fmaf(u.y, su, bu) + fmaf(v.y, sv, bv); o.y = siluf_(z);
        z = fmaf(u.z, su, bu) + fmaf(v.z, sv, bv); o.z = siluf_(z);
        z = fmaf(u.w, su, bu) + fmaf(v.w, sv, bv); o.w = siluf_(z);
    }
    *(float4*)&out[base] = o;
}

// ---------------- launch ----------------
extern "C" void kernel_launch(void* const* d_in, const int* in_sizes, int n_in,
                              void* d_out, int out_size) {
    const float* x        = (const float*)d_in[0];
    const float* dce      = (const float*)d_in[1];
    const float* w_dce    = (const float*)d_in[2];
    const float* b_dce    = (const float*)d_in[3];
    const float* w_ch     = (const float*)d_in[4];
    const float* w_shrink = (const float*)d_in[5];
    const float* b_shrink = (const float*)d_in[6];
    const float* w_expand = (const float*)d_in[7];
    const float* b_expand = (const float*)d_in[8];
    const float* w_conv1  = (const float*)d_in[9];
    const float* g_bn1    = (const float*)d_in[10];
    const float* be_bn1   = (const float*)d_in[11];
    const float* w_conv2  = (const float*)d_in[12];
    const float* g_bn2    = (const float*)d_in[13];
    const float* be_bn2   = (const float*)d_in[14];
    const float* w_sc     = (const float*)d_in[15];
    const float* g_bns    = (const float*)d_in[16];
    const float* be_bns   = (const float*)d_in[17];
    float* out = (float*)d_out;

    k_spatial<<<BATCH*CHAN, 256>>>(x, w_ch);
    k_mod<<<BATCH, 128>>>(dce, w_dce, b_dce, w_shrink, b_shrink, w_expand, b_expand);
    k_wk<<<(16*4*CHAN + 255)/256, 256>>>(w_conv2, w_sc);
    k_w1t<<<(9*16*4*CHAN + 255)/256, 256>>>(w_conv1);   // also zeroes g_stats
    k_xm<<<(BATCH*64*HWSZ/4 + 255)/256, 256>>>(x);
    k_conv1_mma<<<dim3(32, 2, BATCH), 256>>>();
    k_prep<<<(BATCH*64*HWSZ/4 + 255)/256, 256>>>(g_bn1, be_bn1);
    k_gemm_mma2<<<dim3(BATCH*HH, 2), 256>>>();
    k_final<<<(BATCH*CHAN*HWSZ/4 + 255)/256, 256>>>(out, g_bn2, be_bn2, g_bns, be_bns);
}

// round 14
// speedup vs baseline: 1.7584x; 1.0332x over previous
#include <cuda_runtime.h>
#include <cuda_fp16.h>
#include <math.h>
#include <stdint.h>

#define BATCH 16
#define CHAN  256
#define HH    64
#define WW    64
#define HWSZ  4096
#define NHW   65536   // BATCH*HH*WW
#define EPSBN 1e-5f

// ---------------- scratch (device globals; no allocation allowed) ----------------
// interleaved uint2 element at slot (b, kblk, p4, hw):
//   .x = half2(ch 16*kblk+2*p4,   ch 16*kblk+2*p4+1)
//   .y = half2(ch 16*kblk+2*p4+8, ch 16*kblk+2*p4+9)
__device__ __align__(16) uint2 g_t12[BATCH*64*HWSZ];      // conv1 out (half, interleaved)
__device__ __align__(16) uint2 g_u2 [BATCH*64*HWSZ];      // conv2 out (half, interleaved)
__device__ __align__(16) uint2 g_v2 [BATCH*64*HWSZ];      // shortcut out (half, interleaved)
__device__ __align__(16) uint2 g_a2 [BATCH*64*HWSZ];      // silu(bn1(t1)) interleaved
__device__ __align__(16) uint2 g_xm2[BATCH*64*HWSZ];      // x*mod interleaved
__device__ __align__(16) uint2 g_w2p [16*4*CHAN];         // w_conv2 [kblk][p4][co]
__device__ __align__(16) uint2 g_wscp[16*4*CHAN];         // w_sc    [kblk][p4][co]
__device__ __align__(16) uint2 g_w1p[9*16*4*CHAN];        // w_conv1 [tap][kblk][p4][co]
__device__ float g_spatial[BATCH*CHAN];
__device__ float g_mod    [BATCH*CHAN];
// [0:C) sum_t1, [C:2C) sq_t1, [2C:3C) sum_u, [3C:4C) sq_u, [4C:5C) sum_v, [5C:6C) sq_v
__device__ float g_stats[6*CHAN];

__device__ __forceinline__ float sigmoidf_(float z) { return 1.f / (1.f + expf(-z)); }
__device__ __forceinline__ float siluf_(float z)    { return z / (1.f + expf(-z)); }

__device__ __forceinline__ uint32_t packh2(float lo, float hi) {
    __half2 h = __floats2half2_rn(lo, hi);
    return *reinterpret_cast<uint32_t*>(&h);
}
__device__ __forceinline__ float2 unpackh2(uint32_t u) {
    __half2 h = *reinterpret_cast<__half2*>(&u);
    return __half22float2(h);
}

// fp16 m16n8k16 MMA with fp32 accumulate
__device__ __forceinline__ void mma_f16(float* c, uint32_t a0, uint32_t a1,
                                        uint32_t a2, uint32_t a3,
                                        uint32_t b0, uint32_t b1) {
    asm volatile(
        "mma.sync.aligned.m16n8k16.row.col.f32.f16.f16.f32 "
        "{%0,%1,%2,%3}, {%4,%5,%6,%7}, {%8,%9}, {%0,%1,%2,%3};"
        : "+f"(c[0]), "+f"(c[1]), "+f"(c[2]), "+f"(c[3])
        : "r"(a0), "r"(a1), "r"(a2), "r"(a3), "r"(b0), "r"(b1));
}

__device__ __forceinline__ uint32_t smem_addr_u32(const void* p) {
    uint32_t a;
    asm("{ .reg .u64 t; cvta.to.shared.u64 t, %1; cvt.u32.u64 %0, t; }"
        : "=r"(a) : "l"(p));
    return a;
}
__device__ __forceinline__ void cp_async8_zfill(uint32_t dst, const void* src, int srcsz) {
    asm volatile("cp.async.ca.shared.global [%0], [%1], 8, %2;"
                 :: "r"(dst), "l"(src), "r"(srcsz));
}
__device__ __forceinline__ void cp_async16(uint32_t dst, const void* src) {
    asm volatile("cp.async.cg.shared.global [%0], [%1], 16;" :: "r"(dst), "l"(src));
}
__device__ __forceinline__ void cp_async_commit_wait() {
    asm volatile("cp.async.commit_group;");
    asm volatile("cp.async.wait_group 0;" ::: "memory");
}

// ---------------- spatial proj via edge-sum decomposition ----------------
__global__ void k_spatial(const float* __restrict__ x, const float* __restrict__ w_ch) {
    int bc = blockIdx.x;
    int c  = bc & (CHAN-1);
    const float* xp = x + (size_t)bc * HWSZ;
    int tid = threadIdx.x;
    int w = tid & 63;

    float T = 0.f, R0 = 0.f, R1 = 0.f, C0 = 0.f, C1 = 0.f;
    for (int i = tid; i < HWSZ; i += 256) {
        int h = i >> 6;
        float v = xp[i];
        T += v;
        if (h == 0)  R0 += v;
        if (h == 63) R1 += v;
        if (w == 0)  C0 += v;
        if (w == 63) C1 += v;
    }
    __shared__ float red[5];
    if (tid < 5) red[tid] = 0.f;
    __syncthreads();
#pragma unroll
    for (int o = 16; o > 0; o >>= 1) {
        T  += __shfl_xor_sync(0xffffffffu, T,  o);
        R0 += __shfl_xor_sync(0xffffffffu, R0, o);
        R1 += __shfl_xor_sync(0xffffffffu, R1, o);
        C0 += __shfl_xor_sync(0xffffffffu, C0, o);
        C1 += __shfl_xor_sync(0xffffffffu, C1, o);
    }
    if ((tid & 31) == 0) {
        atomicAdd(&red[0], T);
        atomicAdd(&red[1], R0);
        atomicAdd(&red[2], R1);
        atomicAdd(&red[3], C0);
        atomicAdd(&red[4], C1);
    }
    __syncthreads();
    if (tid == 0) {
        float Tt = red[0], tR0 = red[1], tR1 = red[2], tC0 = red[3], tC1 = red[4];
        float c00 = xp[0], c0W = xp[63], cH0 = xp[63*64], cHW = xp[4095];
        float acc = 0.f;
#pragma unroll
        for (int t = 0; t < 9; t++) {
            int dy = t / 3 - 1, dx = t % 3 - 1;
            float s = Tt;
            if (dy == 1)  s -= tR0; else if (dy == -1) s -= tR1;
            if (dx == 1)  s -= tC0; else if (dx == -1) s -= tC1;
            if (dy == 1  && dx == 1)  s += c00;
            if (dy == 1  && dx == -1) s += c0W;
            if (dy == -1 && dx == 1)  s += cH0;
            if (dy == -1 && dx == -1) s += cHW;
            acc += w_ch[c*9 + t] * s;
        }
        g_spatial[bc] = acc * (1.f / (float)HWSZ);
    }
}

// ---------------- gate MLP -> g_mod ----------------
__global__ void k_mod(const float* __restrict__ dce, const float* __restrict__ w_dce,
                      const float* __restrict__ b_dce, const float* __restrict__ w_sh,
                      const float* __restrict__ b_sh, const float* __restrict__ w_ex,
                      const float* __restrict__ b_ex) {
    int b = blockIdx.x;
    int t = threadIdx.x;
    __shared__ float pooled[128];
    __shared__ float mbuf[256];
    __shared__ float hbuf[128];

    {
        float s = 0.f;
        const float* dp = dce + (size_t)b * 100 * 128 + t;
        for (int l = 0; l < 100; l++) s += dp[l * 128];
        pooled[t] = s * 0.01f;
    }
    __syncthreads();

    for (int co = t; co < 256; co += 128) {
        float a = b_dce[co];
        const float* wr = w_dce + (size_t)co * 128;
        for (int j = 0; j < 128; j++) a += pooled[j] * wr[j];
        mbuf[co] = a * g_spatial[b*CHAN + co];
    }
    __syncthreads();

    {
        float a = b_sh[t];
        const float* wr = w_sh + (size_t)t * 256;
        for (int i = 0; i < 256; i++) a += mbuf[i] * wr[i];
        hbuf[t] = fmaxf(a, 0.f);
    }
    __syncthreads();

    for (int co = t; co < 256; co += 128) {
        float a = b_ex[co];
        const float* wr = w_ex + (size_t)co * 128;
        for (int i = 0; i < 128; i++) a += hbuf[i] * wr[i];
        g_mod[b*CHAN + co] = sigmoidf_(a);
    }
}

// ---------------- 1x1 weights -> interleaved uint2 [kblk][p4][co] ----------------
__global__ void k_wk(const float* __restrict__ w2, const float* __restrict__ wsc) {
    int idx = blockIdx.x * blockDim.x + threadIdx.x;
    if (idx >= 16*4*CHAN) return;
    int co   = idx & 255;
    int p4   = (idx >> 8) & 3;
    int kblk = idx >> 10;
    int cA = 16*kblk + 2*p4;
    const float* r2 = w2  + (size_t)co*CHAN;
    const float* rs = wsc + (size_t)co*CHAN;
    g_w2p [idx] = make_uint2(packh2(r2[cA], r2[cA+1]), packh2(r2[cA+8], r2[cA+9]));
    g_wscp[idx] = make_uint2(packh2(rs[cA], rs[cA+1]), packh2(rs[cA+8], rs[cA+9]));
}

// ---------------- conv1 weights -> uint2 [tap][kblk][p4][co]; also zero stats ------------
__global__ void k_w1t(const float* __restrict__ w1) {
    int idx = blockIdx.x * blockDim.x + threadIdx.x;
    if (idx < 6*CHAN) g_stats[idx] = 0.f;
    if (idx >= 9*16*4*CHAN) return;
    int co   = idx & 255;
    int p4   = (idx >> 8) & 3;
    int kblk = (idx >> 10) & 15;
    int tap  = idx >> 14;
    int cA = 16*kblk + 2*p4;
    const float* wr = w1 + (size_t)co*2304;
    g_w1p[idx] = make_uint2(
        packh2(wr[cA*9 + tap],     wr[(cA+1)*9 + tap]),
        packh2(wr[(cA+8)*9 + tap], wr[(cA+9)*9 + tap]));
}

// ---------------- xm = interleaved half2(x*mod) ----------------
__global__ void k_xm(const float* __restrict__ x) {
    int i4 = blockIdx.x * blockDim.x + threadIdx.x;
    size_t base = (size_t)i4 * 4;       // uint2-element index
    if (base >= (size_t)BATCH*64*HWSZ) return;
    int hw   = (int)(base & 4095);
    int p4   = (int)((base >> 12) & 3);
    int kblk = (int)((base >> 14) & 15);
    int b    = (int)(base >> 18);
    int cA = 16*kblk + 2*p4;
    float m0 = g_mod[b*CHAN + cA],   m1 = g_mod[b*CHAN + cA+1];
    float m2 = g_mod[b*CHAN + cA+8], m3 = g_mod[b*CHAN + cA+9];
    const float* x0 = x + ((size_t)b*CHAN + cA)*HWSZ + hw;
    float4 a0 = *(const float4*)x0;
    float4 a1 = *(const float4*)(x0 + HWSZ);
    float4 b0 = *(const float4*)(x0 + 8*HWSZ);
    float4 b1 = *(const float4*)(x0 + 9*HWSZ);
    uint4 o0, o1;
    o0.x = packh2(a0.x*m0, a1.x*m1); o0.y = packh2(b0.x*m2, b1.x*m3);
    o0.z = packh2(a0.y*m0, a1.y*m1); o0.w = packh2(b0.y*m2, b1.y*m3);
    o1.x = packh2(a0.z*m0, a1.z*m1); o1.y = packh2(b0.z*m2, b1.z*m3);
    o1.z = packh2(a0.w*m0, a1.w*m1); o1.w = packh2(b0.w*m2, b1.w*m3);
    uint4* dst = reinterpret_cast<uint4*>(&g_xm2[base]);
    dst[0] = o0;
    dst[1] = o1;
}

// ---------------- conv1 via fp16 mma m16n8k16, pair-interleaved smem ----------------
// Block tile: M=128 pixels (16 rows x 8 cols), N=128 couts, K-stage = 16 ch (kblk).
// Warps 4(M) x 2(N). All fragment loads are LDS.64, conflict-free pitches.
#define PST2 200                          // uint2 per p4 patch row (18*10=180 + pad), %32==8
#define BST2 136                          // uint2 per B row (128 co + pad), %32==8
__global__ void __launch_bounds__(256) k_conv1_mma() {
    __shared__ __align__(16) uint2 s_in[4*PST2];    // [p4][18x10 patch]
    __shared__ __align__(16) uint2 s_b [36*BST2];   // [tap*4 + p4][co]
    __shared__ float s_sum[128], s_sq[128];

    int b    = blockIdx.z;
    int co0  = blockIdx.y * 128;
    int tile = blockIdx.x;
    int th0  = (tile >> 3) * 16;
    int tw0  = (tile & 7) * 8;

    int tid  = threadIdx.x;
    int warp = tid >> 5;
    int lane = tid & 31;
    int gid  = lane >> 2;
    int tq   = lane & 3;
    int wm   = warp & 3;
    int wn   = warp >> 2;

    if (tid < 128) { s_sum[tid] = 0.f; s_sq[tid] = 0.f; }

    uint32_t s_in_a = smem_addr_u32(s_in);
    uint32_t s_b_a  = smem_addr_u32(s_b);

    float acc[2][8][4];
#pragma unroll
    for (int t = 0; t < 2; t++)
#pragma unroll
        for (int j = 0; j < 8; j++)
#pragma unroll
            for (int k = 0; k < 4; k++) acc[t][j][k] = 0.f;

    for (int kblk = 0; kblk < 16; kblk++) {      // 16 stages of 16 channels
        __syncthreads();

        // ---- A halo patch: 4 p4-rows x 180, 8B cp.async (zfill OOB) ----
        for (int idx = tid; idx < 4*180; idx += 256) {
            int p4 = idx / 180, r = idx - p4*180;
            int iy = r / 10, ix = r - iy*10;
            int gh = th0 + iy - 1, gw = tw0 + ix - 1;
            bool ok = (gh >= 0) && (gh < HH) && (gw >= 0) && (gw < WW);
            const uint2* src = g_xm2 + (size_t)((b*16 + kblk)*4 + p4)*HWSZ
                             + (ok ? (gh*WW + gw) : 0);
            cp_async8_zfill(s_in_a + (uint32_t)(p4*PST2 + r)*8u, src, ok ? 8 : 0);
        }
        // ---- B: 9 taps x 4 p4 x 128 co uint2 = 2304 x 16B cp.async ----
        for (int idx2 = tid; idx2 < 2304; idx2 += 256) {
            int lin = idx2 * 2;               // uint2 units
            int tap = lin >> 9;               // 512 uint2 per tap
            int rem = lin & 511;
            int p4  = rem >> 7;
            int coU = rem & 127;              // even
            const uint2* src = g_w1p + (size_t)((tap*16 + kblk)*4 + p4)*256
                             + co0 + coU;
            cp_async16(s_b_a + (uint32_t)((tap*4 + p4)*BST2 + coU)*8u, src);
        }
        cp_async_commit_wait();
        __syncthreads();

        // ---- mainloop: 9 taps x 16 MMAs, all LDS.64 fragments ----
        for (int tap = 0; tap < 9; tap++) {
            int ky = tap / 3, kx = tap - ky*3;
            uint2 aL[2], aH[2];
#pragma unroll
            for (int t = 0; t < 2; t++) {
                int arow = (wm*4 + 2*t + ky)*10 + gid + kx;
                const uint2* ap = s_in + tq*PST2 + arow;
                aL[t] = ap[0];     // {a0 (k-lo), a2 (k-hi)} at pixel row
                aH[t] = ap[10];    // {a1, a3} at pixel row+8
            }
            const uint2* bp = s_b + (tap*4 + tq)*BST2 + wn*64 + gid;
#pragma unroll
            for (int j = 0; j < 8; j++) {
                uint2 bb = bp[j*8];
#pragma unroll
                for (int t = 0; t < 2; t++)
                    mma_f16(acc[t][j], aL[t].x, aH[t].x, aL[t].y, aH[t].y, bb.x, bb.y);
            }
        }
    }

    // ---- store (interleaved half2) + bn1 partial stats (from fp32 accs) ----
    int px = tw0 + gid;
#pragma unroll
    for (int t = 0; t < 2; t++) {
        int gr = th0 + wm*4 + t*2;
#pragma unroll
        for (int jp = 0; jp < 4; jp++) {
            int j = jp*2;
            int co_lo = co0 + wn*64 + j*8 + tq*2;    // j even -> lo pair
            int kblk  = co_lo >> 4;                  // p4 == tq
            size_t slot = (size_t)((b*16 + kblk)*4 + tq)*HWSZ + (size_t)gr*WW + px;
            g_t12[slot]      = make_uint2(packh2(acc[t][j][0],   acc[t][j][1]),
                                          packh2(acc[t][j+1][0], acc[t][j+1][1]));
            g_t12[slot + WW] = make_uint2(packh2(acc[t][j][2],   acc[t][j][3]),
                                          packh2(acc[t][j+1][2], acc[t][j+1][3]));
        }
        // stats over all 8 j (fp32 exact)
#pragma unroll
        for (int j = 0; j < 8; j++) {
            int col = wn*64 + j*8 + tq*2;
            float c0v = acc[t][j][0], c1v = acc[t][j][1];
            float c2v = acc[t][j][2], c3v = acc[t][j][3];
            float s0 = c0v + c2v;
            float s1 = c1v + c3v;
            float q0 = c0v*c0v + c2v*c2v;
            float q1 = c1v*c1v + c3v*c3v;
#pragma unroll
            for (int o = 4; o < 32; o <<= 1) {
                s0 += __shfl_xor_sync(0xffffffffu, s0, o);
                s1 += __shfl_xor_sync(0xffffffffu, s1, o);
                q0 += __shfl_xor_sync(0xffffffffu, q0, o);
                q1 += __shfl_xor_sync(0xffffffffu, q1, o);
            }
            if (gid == 0) {
                atomicAdd(&s_sum[col],     s0);
                atomicAdd(&s_sum[col + 1], s1);
                atomicAdd(&s_sq [col],     q0);
                atomicAdd(&s_sq [col + 1], q1);
            }
        }
    }
    __syncthreads();
    if (tid < 128) {
        atomicAdd(&g_stats[co0 + tid],        s_sum[tid]);
        atomicAdd(&g_stats[CHAN + co0 + tid], s_sq[tid]);
    }
}

// ---------------- prep: g_a2 = interleaved half2(silu(bn1(t12))) ----------------
__global__ void k_prep(const float* __restrict__ g1, const float* __restrict__ be1) {
    int i4 = blockIdx.x * blockDim.x + threadIdx.x;
    size_t base = (size_t)i4 * 4;       // uint2-element index
    if (base >= (size_t)BATCH*64*HWSZ) return;
    int p4   = (int)((base >> 12) & 3);
    int kblk = (int)((base >> 14) & 15);
    int cA = 16*kblk + 2*p4;

    float sc[4], sh[4];
    int cs[4] = {cA, cA+1, cA+8, cA+9};
#pragma unroll
    for (int i = 0; i < 4; i++) {
        int c = cs[i];
        float mean = g_stats[c] * (1.f/(float)NHW);
        float var  = g_stats[CHAN+c] * (1.f/(float)NHW) - mean*mean;
        sc[i] = g1[c] * rsqrtf(var + EPSBN);
        sh[i] = be1[c] - mean*sc[i];
    }
    const uint4* src = reinterpret_cast<const uint4*>(&g_t12[base]);
    uint4 t0 = src[0], t1 = src[1];
    uint4 o0, o1;
    {
        float2 lo, hi;
        lo = unpackh2(t0.x); hi = unpackh2(t0.y);
        o0.x = packh2(siluf_(fmaf(lo.x, sc[0], sh[0])), siluf_(fmaf(lo.y, sc[1], sh[1])));
        o0.y = packh2(siluf_(fmaf(hi.x, sc[2], sh[2])), siluf_(fmaf(hi.y, sc[3], sh[3])));
        lo = unpackh2(t0.z); hi = unpackh2(t0.w);
        o0.z = packh2(siluf_(fmaf(lo.x, sc[0], sh[0])), siluf_(fmaf(lo.y, sc[1], sh[1])));
        o0.w = packh2(siluf_(fmaf(hi.x, sc[2], sh[2])), siluf_(fmaf(hi.y, sc[3], sh[3])));
        lo = unpackh2(t1.x); hi = unpackh2(t1.y);
        o1.x = packh2(siluf_(fmaf(lo.x, sc[0], sh[0])), siluf_(fmaf(lo.y, sc[1], sh[1])));
        o1.y = packh2(siluf_(fmaf(hi.x, sc[2], sh[2])), siluf_(fmaf(hi.y, sc[3], sh[3])));
        lo = unpackh2(t1.z); hi = unpackh2(t1.w);
        o1.z = packh2(siluf_(fmaf(lo.x, sc[0], sh[0])), siluf_(fmaf(lo.y, sc[1], sh[1])));
        o1.w = packh2(siluf_(fmaf(hi.x, sc[2], sh[2])), siluf_(fmaf(hi.y, sc[3], sh[3])));
    }
    uint4* dst = reinterpret_cast<uint4*>(&g_a2[base]);
    dst[0] = o0;
    dst[1] = o1;
}

// ---------------- fused 1x1 GEMMs via fp16 mma, pair-interleaved ----------------
//   path 0: u = w2 @ g_a2     path 1: v = wsc @ g_xm2
// grid (B*H = 1024, 2). Block: M=64 pixels (one row), N=256 couts, K-iter = 2 kblks.
#define APC2 72    // uint2 per A row (64 px + pad), %32==8
#define WPC2 264   // uint2 per W row (256 co + pad), %32==8
__global__ void __launch_bounds__(256) k_gemm_mma2() {
    __shared__ __align__(16) uint2 sA[8*APC2];
    __shared__ __align__(16) uint2 sW[8*WPC2];
    __shared__ float s_s[CHAN], s_q[CHAN];

    int bh   = blockIdx.x;
    int b    = bh >> 6;
    int h    = bh & 63;
    int path = blockIdx.y;          // 0 = u, 1 = v
    int tid  = threadIdx.x;
    int warp = tid >> 5;
    int lane = tid & 31;
    int gid  = lane >> 2;
    int tq   = lane & 3;
    int mt   = (warp & 1) * 32;
    int n0   = (warp >> 1) * 64;

    s_s[tid] = 0.f;
    s_q[tid] = 0.f;

    float acc[2][8][4];
#pragma unroll
    for (int t = 0; t < 2; t++)
#pragma unroll
        for (int j = 0; j < 8; j++)
#pragma unroll
            for (int k = 0; k < 4; k++) acc[t][j][k] = 0.f;

    const uint2* wsrc = path ? g_wscp : g_w2p;
    const uint2* asrc = path ? g_xm2  : g_a2;
    size_t arow0 = (size_t)b*64*HWSZ + h*WW;   // + (kblk*4+p4)*HWSZ + px

    for (int kb0 = 0; kb0 < 16; kb0 += 2) {    // 8 iterations of 32 channels
        __syncthreads();
        // A tile: 8 rows (2 kblk x 4 p4) x 64 px
        for (int idx4 = tid; idx4 < 256; idx4 += 256) {
            int row = idx4 >> 5, px2 = (idx4 & 31) * 2;
            *reinterpret_cast<uint4*>(sA + row*APC2 + px2) =
                *reinterpret_cast<const uint4*>(asrc + arow0 + (size_t)(kb0*4 + row)*HWSZ + px2);
        }
        // W tile: 8 rows x 256 co
        for (int idx4 = tid; idx4 < 1024; idx4 += 256) {
            int row = idx4 >> 7, co2 = (idx4 & 127) * 2;
            *reinterpret_cast<uint4*>(sW + row*WPC2 + co2) =
                *reinterpret_cast<const uint4*>(wsrc + (size_t)(kb0*4 + row)*256 + co2);
        }
        __syncthreads();

#pragma unroll
        for (int grp = 0; grp < 2; grp++) {
            uint2 aL[2], aH[2];
#pragma unroll
            for (int t = 0; t < 2; t++) {
                const uint2* ap = sA + (grp*4 + tq)*APC2 + mt + t*16 + gid;
                aL[t] = ap[0];
                aH[t] = ap[8];     // m+8
            }
            const uint2* bp = sW + (grp*4 + tq)*WPC2 + n0 + gid;
#pragma unroll
            for (int j = 0; j < 8; j++) {
                uint2 bb = bp[j*8];
#pragma unroll
                for (int t = 0; t < 2; t++)
                    mma_f16(acc[t][j], aL[t].x, aH[t].x, aL[t].y, aH[t].y, bb.x, bb.y);
            }
        }
    }

    // ---- store (interleaved half2) + stats (fp32) ----
    uint2* gout = path ? g_v2 : g_u2;
#pragma unroll
    for (int t = 0; t < 2; t++) {
        int p = mt + t*16 + gid;
#pragma unroll
        for (int jp = 0; jp < 4; jp++) {
            int j = jp*2;
            int co_lo = n0 + j*8 + tq*2;             // even j -> lo pair; p4 == tq
            int kblk  = co_lo >> 4;
            size_t slot = (size_t)((b*16 + kblk)*4 + tq)*HWSZ + (size_t)h*WW + p;
            gout[slot]     = make_uint2(packh2(acc[t][j][0],   acc[t][j][1]),
                                        packh2(acc[t][j+1][0], acc[t][j+1][1]));
            gout[slot + 8] = make_uint2(packh2(acc[t][j][2],   acc[t][j][3]),
                                        packh2(acc[t][j+1][2], acc[t][j+1][3]));
        }
#pragma unroll
        for (int j = 0; j < 8; j++) {
            int co = n0 + j*8 + tq*2;
            float c0v = acc[t][j][0], c1v = acc[t][j][1];
            float c2v = acc[t][j][2], c3v = acc[t][j][3];
            float s0 = c0v + c2v;
            float s1 = c1v + c3v;
            float q0 = c0v*c0v + c2v*c2v;
            float q1 = c1v*c1v + c3v*c3v;
#pragma unroll
            for (int o = 4; o < 32; o <<= 1) {
                s0 += __shfl_xor_sync(0xffffffffu, s0, o);
                s1 += __shfl_xor_sync(0xffffffffu, s1, o);
                q0 += __shfl_xor_sync(0xffffffffu, q0, o);
                q1 += __shfl_xor_sync(0xffffffffu, q1, o);
            }
            if (gid == 0) {
                atomicAdd(&s_s[co],     s0);
                atomicAdd(&s_s[co + 1], s1);
                atomicAdd(&s_q[co],     q0);
                atomicAdd(&s_q[co + 1], q1);
            }
        }
    }
    __syncthreads();
    {
        int soff = 2*CHAN + 2*CHAN*path;
        atomicAdd(&g_stats[soff + tid],        s_s[tid]);
        atomicAdd(&g_stats[soff + CHAN + tid], s_q[tid]);
    }
}

// ---------------- final: out = silu(bn2(u) + bns(v)), interleaved half2 inputs ----------
__global__ void k_final(float* __restrict__ out,
                        const float* __restrict__ g2, const float* __restrict__ be2,
                        const float* __restrict__ gs, const float* __restrict__ bes) {
    int i4 = blockIdx.x * blockDim.x + threadIdx.x;
    size_t base = (size_t)i4 * 4;       // uint2-element index
    if (base >= (size_t)BATCH*64*HWSZ) return;
    int hw   = (int)(base & 4095);
    int p4   = (int)((base >> 12) & 3);
    int kblk = (int)((base >> 14) & 15);
    int b    = (int)(base >> 18);
    int cA = 16*kblk + 2*p4;
    int cs[4] = {cA, cA+1, cA+8, cA+9};

    float su[4], bu[4], sv[4], bv[4];
#pragma unroll
    for (int i = 0; i < 4; i++) {
        int c = cs[i];
        float mu = g_stats[2*CHAN + c] * (1.f/(float)NHW);
        float vu = g_stats[3*CHAN + c] * (1.f/(float)NHW) - mu*mu;
        su[i] = g2[c] * rsqrtf(vu + EPSBN);
        bu[i] = be2[c] - mu*su[i];
        float mv = g_stats[4*CHAN + c] * (1.f/(float)NHW);
        float vv = g_stats[5*CHAN + c] * (1.f/(float)NHW) - mv*mv;
        sv[i] = gs[c] * rsqrtf(vv + EPSBN);
        bv[i] = bes[c] - mv*sv[i];
    }

    const uint4* usrc = reinterpret_cast<const uint4*>(&g_u2[base]);
    const uint4* vsrc = reinterpret_cast<const uint4*>(&g_v2[base]);
    uint4 U0 = usrc[0], U1 = usrc[1];
    uint4 V0 = vsrc[0], V1 = vsrc[1];

    // e0..e3 correspond to hw..hw+3; each has lo(ch 0,1) and hi(ch 2,3)
    float4 oc[4];   // oc[i] = output for channel cs[i], pixels hw..hw+3
    {
        float2 ul, uh, vl, vh;
        // e0
        ul = unpackh2(U0.x); uh = unpackh2(U0.y);
        vl = unpackh2(V0.x); vh = unpackh2(V0.y);
        oc[0].x = siluf_(fmaf(ul.x, su[0], bu[0]) + fmaf(vl.x, sv[0], bv[0]));
        oc[1].x = siluf_(fmaf(ul.y, su[1], bu[1]) + fmaf(vl.y, sv[1], bv[1]));
        oc[2].x = siluf_(fmaf(uh.x, su[2], bu[2]) + fmaf(vh.x, sv[2], bv[2]));
        oc[3].x = siluf_(fmaf(uh.y, su[3], bu[3]) + fmaf(vh.y, sv[3], bv[3]));
        // e1
        ul = unpackh2(U0.z); uh = unpackh2(U0.w);
        vl = unpackh2(V0.z); vh = unpackh2(V0.w);
        oc[0].y = siluf_(fmaf(ul.x, su[0], bu[0]) + fmaf(vl.x, sv[0], bv[0]));
        oc[1].y = siluf_(fmaf(ul.y, su[1], bu[1]) + fmaf(vl.y, sv[1], bv[1]));
        oc[2].y = siluf_(fmaf(uh.x, su[2], bu[2]) + fmaf(vh.x, sv[2], bv[2]));
        oc[3].y = siluf_(fmaf(uh.y, su[3], bu[3]) + fmaf(vh.y, sv[3], bv[3]));
        // e2
        ul = unpackh2(U1.x); uh = unpackh2(U1.y);
        vl = unpackh2(V1.x); vh = unpackh2(V1.y);
        oc[0].z = siluf_(fmaf(ul.x, su[0], bu[0]) + fmaf(vl.x, sv[0], bv[0]));
        oc[1].z = siluf_(fmaf(ul.y, su[1], bu[1]) + fmaf(vl.y, sv[1], bv[1]));
        oc[2].z = siluf_(fmaf(uh.x, su[2], bu[2]) + fmaf(vh.x, sv[2], bv[2]));
        oc[3].z = siluf_(fmaf(uh.y, su[3], bu[3]) + fmaf(vh.y, sv[3], bv[3]));
        // e3
        ul = unpackh2(U1.z); uh = unpackh2(U1.w);
        vl = unpackh2(V1.z); vh = unpackh2(V1.w);
        oc[0].w = siluf_(fmaf(ul.x, su[0], bu[0]) + fmaf(vl.x, sv[0], bv[0]));
        oc[1].w = siluf_(fmaf(ul.y, su[1], bu[1]) + fmaf(vl.y, sv[1], bv[1]));
        oc[2].w = siluf_(fmaf(uh.x, su[2], bu[2]) + fmaf(vh.x, sv[2], bv[2]));
        oc[3].w = siluf_(fmaf(uh.y, su[3], bu[3]) + fmaf(vh.y, sv[3], bv[3]));
    }
#pragma unroll
    for (int i = 0; i < 4; i++) {
        *reinterpret_cast<float4*>(out + ((size_t)b*CHAN + cs[i])*HWSZ + hw) = oc[i];
    }
}

// ---------------- launch ----------------
extern "C" void kernel_launch(void* const* d_in, const int* in_sizes, int n_in,
                              void* d_out, int out_size) {
    const float* x        = (const float*)d_in[0];
    const float* dce      = (const float*)d_in[1];
    const float* w_dce    = (const float*)d_in[2];
    const float* b_dce    = (const float*)d_in[3];
    const float* w_ch     = (const float*)d_in[4];
    const float* w_shrink = (const float*)d_in[5];
    const float* b_shrink = (const float*)d_in[6];
    const float* w_expand = (const float*)d_in[7];
    const float* b_expand = (const float*)d_in[8];
    const float* w_conv1  = (const float*)d_in[9];
    const float* g_bn1    = (const float*)d_in[10];
    const float* be_bn1   = (const float*)d_in[11];
    const float* w_conv2  = (const float*)d_in[12];
    const float* g_bn2    = (const float*)d_in[13];
    const float* be_bn2   = (const float*)d_in[14];
    const float* w_sc     = (const float*)d_in[15];
    const float* g_bns    = (const float*)d_in[16];
    const float* be_bns   = (const float*)d_in[17];
    float* out = (float*)d_out;

    k_spatial<<<BATCH*CHAN, 256>>>(x, w_ch);
    k_mod<<<BATCH, 128>>>(dce, w_dce, b_dce, w_shrink, b_shrink, w_expand, b_expand);
    k_wk<<<(16*4*CHAN + 255)/256, 256>>>(w_conv2, w_sc);
    k_w1t<<<(9*16*4*CHAN + 255)/256, 256>>>(w_conv1);   // also zeroes g_stats
    k_xm<<<(BATCH*64*HWSZ/4 + 255)/256, 256>>>(x);
    k_conv1_mma<<<dim3(32, 2, BATCH), 256>>>();
    k_prep<<<(BATCH*64*HWSZ/4 + 255)/256, 256>>>(g_bn1, be_bn1);
    k_gemm_mma2<<<dim3(BATCH*HH, 2), 256>>>();
    k_final<<<(BATCH*64*HWSZ/4 + 255)/256, 256>>>(out, g_bn2, be_bn2, g_bns, be_bns);
}